// round 12
// baseline (speedup 1.0000x reference)
#include <cuda_runtime.h>
#include <cuda.h>

#define BN 2
#define LN 12288
#define KN 32
#define IN 768
#define CT 128
#define CA 16
#define RMS_EPS 1e-6f

typedef unsigned long long u64;

// Scratch (allocs are banned; device globals are the sanctioned workaround)
__device__ __align__(128) float g_Sl[BN * LN * CA];   // 1.5 MB
__device__ __align__(128) float g_Sm[BN * LN * CA];   // 1.5 MB
__device__ __align__(128) float g_Zp[(size_t)IN * IN * CA];  // 37.75 MB
__device__ float4 g_mp[LN];                           // motif pos + meta bits
__device__ float4 g_rp[LN];                           // ref pos

// ---- packed f32x2 helpers (sm_100+) ---------------------------------------
__device__ __forceinline__ u64 pack2(float a, float b) {
    u64 v;
    asm("mov.b64 %0, {%1, %2};" : "=l"(v) : "r"(__float_as_uint(a)), "r"(__float_as_uint(b)));
    return v;
}
__device__ __forceinline__ void unpack2(u64 v, float& a, float& b) {
    unsigned x, y;
    asm("mov.b64 {%0, %1}, %2;" : "=r"(x), "=r"(y) : "l"(v));
    a = __uint_as_float(x); b = __uint_as_float(y);
}
__device__ __forceinline__ void fma2(u64& d, u64 a, u64 b) {
    asm("fma.rn.f32x2 %0, %1, %2, %0;" : "+l"(d) : "l"(a), "l"(b));
}
__device__ __forceinline__ void cp_async16(void* smem_dst, const void* gmem_src) {
    unsigned s = (unsigned)__cvta_generic_to_shared(smem_dst);
    asm volatile("cp.async.cg.shared.global [%0], [%1], 16;\n" :: "r"(s), "l"(gmem_src));
}
__device__ __forceinline__ void cp_async_wait_all() {
    asm volatile("cp.async.commit_group;\ncp.async.wait_group 0;\n" ::: "memory");
}
__device__ __forceinline__ unsigned smem_u32(const void* p) {
    return (unsigned)__cvta_generic_to_shared(p);
}
__device__ __forceinline__ void mbar_init(unsigned addr, unsigned count) {
    asm volatile("mbarrier.init.shared.b64 [%0], %1;" :: "r"(addr), "r"(count) : "memory");
}
__device__ __forceinline__ void mbar_expect_tx(unsigned addr, unsigned bytes) {
    asm volatile("mbarrier.arrive.expect_tx.shared.b64 _, [%0], %1;"
                 :: "r"(addr), "r"(bytes) : "memory");
}
__device__ __forceinline__ void mbar_wait(unsigned addr, unsigned parity) {
    asm volatile(
        "{\n\t.reg .pred P;\n"
        "WAIT_%=:\n\t"
        "mbarrier.try_wait.parity.acquire.cta.shared::cta.b64 P, [%0], %1, 0x989680;\n\t"
        "@P bra.uni DONE_%=;\n\t"
        "bra.uni WAIT_%=;\n"
        "DONE_%=:\n\t}"
        :: "r"(addr), "r"(parity) : "memory");
}
__device__ __forceinline__ void tma_load_2d(unsigned dst, const CUtensorMap* map,
                                            int x, int y, unsigned mbar) {
    asm volatile(
        "cp.async.bulk.tensor.2d.shared::cta.global.tile.mbarrier::complete_tx::bytes "
        "[%0], [%1, {%2, %3}], [%4];"
        :: "r"(dst), "l"(map), "r"(x), "r"(y), "r"(mbar) : "memory");
}

// ---------------------------------------------------------------------------
// Kernel 2 (dominant): Z_proc = rmsnorm(Z)*rms_w @ W_z.
// TMA double-buffered pipeline: 512 rows/block, K split in 4 x 128B chunks.
// Each chunk = 2 UTMALDG (rows +0 / +256, box [32 f32, 256], SW128) into a
// 64KB buffer; chunk h+2 issued after compute of h. Replaces 16384 cp.async
// per block (the staging-issue wall that pinned zproc at ~87us) with 8 TMA.
// Compute math identical to R7 (same fp32 order).
// ---------------------------------------------------------------------------
#define ZR3 512
#define ZCHUNK 65536          // bytes per chunk buffer (512 rows x 128B)

__global__ void __launch_bounds__(128) zproc_kernel(
    const __grid_constant__ CUtensorMap tmap,
    const float* __restrict__ rmsw,
    const float* __restrict__ Wz)
{
    extern __shared__ __align__(1024) char sBuf[];     // 2 x 64KB
    __shared__ ulonglong2 sW[CT * 2];                  // cols 0-7
    __shared__ ulonglong2 sW2[CT * 2];                 // cols 8-15
    __shared__ __align__(8) u64 sMbar[2];

    for (int i = threadIdx.x; i < CT * 2; i += 128) {
        int t = i >> 1, p = i & 1;
        float rw = rmsw[t];
        const float* w = Wz + t * CA;
        sW [i] = make_ulonglong2(pack2(rw * w[4 * p + 0], rw * w[4 * p + 1]),
                                 pack2(rw * w[4 * p + 2], rw * w[4 * p + 3]));
        sW2[i] = make_ulonglong2(pack2(rw * w[8 + 4 * p + 0], rw * w[8 + 4 * p + 1]),
                                 pack2(rw * w[8 + 4 * p + 2], rw * w[8 + 4 * p + 3]));
    }

    unsigned mb0 = smem_u32(&sMbar[0]);
    unsigned mb1 = smem_u32(&sMbar[1]);
    unsigned sb  = smem_u32(sBuf);

    if (threadIdx.x == 0) {
        mbar_init(mb0, 1);
        mbar_init(mb1, 1);
        asm volatile("fence.proxy.async.shared::cta;" ::: "memory");
    }
    __syncthreads();

    int blockRow = blockIdx.x * ZR3;

    // prologue: issue chunks 0 and 1
    if (threadIdx.x == 0) {
#pragma unroll
        for (int h = 0; h < 2; h++) {
            unsigned mb = h ? mb1 : mb0;
            mbar_expect_tx(mb, ZCHUNK);
            tma_load_2d(sb + h * ZCHUNK,         &tmap, h * 32, blockRow,       mb);
            tma_load_2d(sb + h * ZCHUNK + 32768, &tmap, h * 32, blockRow + 256, mb);
        }
    }

    int r = threadIdx.x;
    u64 acc[4][8];
#pragma unroll
    for (int k = 0; k < 4; k++)
#pragma unroll
        for (int c = 0; c < 8; c++) acc[k][c] = 0ull;
    float ss[4] = {0.f, 0.f, 0.f, 0.f};

#pragma unroll 1
    for (int h = 0; h < 4; h++) {
        unsigned mb = (h & 1) ? mb1 : mb0;
        mbar_wait(mb, (h >> 1) & 1);

        const char* buf = sBuf + (h & 1) * ZCHUNK;
#pragma unroll
        for (int i = 0; i < 8; i++) {
            // row rw = r + 128k; region = rw>>8 (two 256-row TMA boxes);
            // in-box offset swizzled per SW128.
            float4 v[4];
#pragma unroll
            for (int k = 0; k < 4; k++) {
                int rw = r + 128 * k;
                int region = rw >> 8;
                int rr = rw & 255;
                unsigned off = rr * 128 + i * 16;
                unsigned sw = off ^ ((off >> 3) & 0x70);
                v[k] = *reinterpret_cast<const float4*>(buf + region * 32768 + sw);
            }
            float x0[4] = {v[0].x, v[0].y, v[0].z, v[0].w};
            float x1[4] = {v[1].x, v[1].y, v[1].z, v[1].w};
            float x2[4] = {v[2].x, v[2].y, v[2].z, v[2].w};
            float x3[4] = {v[3].x, v[3].y, v[3].z, v[3].w};
            int tb = h * 32 + i * 4;
#pragma unroll
            for (int e = 0; e < 4; e++) {
                int t = tb + e;
                ulonglong2 wA = sW [t * 2 + 0];
                ulonglong2 wB = sW [t * 2 + 1];
                ulonglong2 wC = sW2[t * 2 + 0];
                ulonglong2 wD = sW2[t * 2 + 1];
                u64 b0 = pack2(x0[e], x0[e]);
                u64 b1 = pack2(x1[e], x1[e]);
                u64 b2 = pack2(x2[e], x2[e]);
                u64 b3 = pack2(x3[e], x3[e]);
                fma2(acc[0][0], b0, wA.x); fma2(acc[0][1], b0, wA.y);
                fma2(acc[0][2], b0, wB.x); fma2(acc[0][3], b0, wB.y);
                fma2(acc[0][4], b0, wC.x); fma2(acc[0][5], b0, wC.y);
                fma2(acc[0][6], b0, wD.x); fma2(acc[0][7], b0, wD.y);
                fma2(acc[1][0], b1, wA.x); fma2(acc[1][1], b1, wA.y);
                fma2(acc[1][2], b1, wB.x); fma2(acc[1][3], b1, wB.y);
                fma2(acc[1][4], b1, wC.x); fma2(acc[1][5], b1, wC.y);
                fma2(acc[1][6], b1, wD.x); fma2(acc[1][7], b1, wD.y);
                fma2(acc[2][0], b2, wA.x); fma2(acc[2][1], b2, wA.y);
                fma2(acc[2][2], b2, wB.x); fma2(acc[2][3], b2, wB.y);
                fma2(acc[2][4], b2, wC.x); fma2(acc[2][5], b2, wC.y);
                fma2(acc[2][6], b2, wD.x); fma2(acc[2][7], b2, wD.y);
                fma2(acc[3][0], b3, wA.x); fma2(acc[3][1], b3, wA.y);
                fma2(acc[3][2], b3, wB.x); fma2(acc[3][3], b3, wB.y);
                fma2(acc[3][4], b3, wC.x); fma2(acc[3][5], b3, wC.y);
                fma2(acc[3][6], b3, wD.x); fma2(acc[3][7], b3, wD.y);
                ss[0] = fmaf(x0[e], x0[e], ss[0]);
                ss[1] = fmaf(x1[e], x1[e], ss[1]);
                ss[2] = fmaf(x2[e], x2[e], ss[2]);
                ss[3] = fmaf(x3[e], x3[e], ss[3]);
            }
        }

        __syncthreads();                               // all lanes done with buffer
        if (h + 2 < 4 && threadIdx.x == 0) {
            int hn = h + 2;
            mbar_expect_tx(mb, ZCHUNK);
            tma_load_2d(sb + (h & 1) * ZCHUNK,         &tmap, hn * 32, blockRow,       mb);
            tma_load_2d(sb + (h & 1) * ZCHUNK + 32768, &tmap, hn * 32, blockRow + 256, mb);
        }
    }

#pragma unroll
    for (int k = 0; k < 4; k++) {
        float scale = rsqrtf(ss[k] * (1.0f / CT) + RMS_EPS);
        float* o = g_Zp + ((size_t)blockIdx.x * ZR3 + r + 128 * k) * CA;
#pragma unroll
        for (int c4 = 0; c4 < 4; c4++) {
            float a0, a1, b0, b1;
            unpack2(acc[k][2 * c4 + 0], a0, a1);
            unpack2(acc[k][2 * c4 + 1], b0, b1);
            reinterpret_cast<float4*>(o)[c4] =
                make_float4(a0 * scale, a1 * scale, b0 * scale, b1 * scale);
        }
    }
}

// fallback zproc (R7-exact) in case the TMA descriptor can't be built
__global__ void __launch_bounds__(128) zproc_fallback_kernel(
    const float* __restrict__ Z,
    const float* __restrict__ rmsw,
    const float* __restrict__ Wz)
{
    __shared__ float4 sX[ZR3 * 5];
    __shared__ ulonglong2 sW[CT * 2];
    __shared__ ulonglong2 sW2[CT * 2];

    for (int i = threadIdx.x; i < CT * 2; i += 128) {
        int t = i >> 1, p = i & 1;
        float rw = rmsw[t];
        const float* w = Wz + t * CA;
        sW [i] = make_ulonglong2(pack2(rw * w[4 * p + 0], rw * w[4 * p + 1]),
                                 pack2(rw * w[4 * p + 2], rw * w[4 * p + 3]));
        sW2[i] = make_ulonglong2(pack2(rw * w[8 + 4 * p + 0], rw * w[8 + 4 * p + 1]),
                                 pack2(rw * w[8 + 4 * p + 2], rw * w[8 + 4 * p + 3]));
    }

    int r = threadIdx.x;
    const float4* src = reinterpret_cast<const float4*>(Z) + (size_t)blockIdx.x * ZR3 * 32;

    u64 acc[4][8];
#pragma unroll
    for (int k = 0; k < 4; k++)
#pragma unroll
        for (int c = 0; c < 8; c++) acc[k][c] = 0ull;
    float ss[4] = {0.f, 0.f, 0.f, 0.f};

#pragma unroll 1
    for (int h = 0; h < 8; h++) {
        __syncthreads();
#pragma unroll 4
        for (int j = threadIdx.x; j < ZR3 * 4; j += 128) {
            int row = j >> 2, col = j & 3;
            cp_async16(&sX[row * 5 + col], src + row * 32 + h * 4 + col);
        }
        cp_async_wait_all();
        __syncthreads();

#pragma unroll
        for (int i = 0; i < 4; i++) {
            float4 v0 = sX[(r      ) * 5 + i];
            float4 v1 = sX[(r + 128) * 5 + i];
            float4 v2 = sX[(r + 256) * 5 + i];
            float4 v3 = sX[(r + 384) * 5 + i];
            float x0[4] = {v0.x, v0.y, v0.z, v0.w};
            float x1[4] = {v1.x, v1.y, v1.z, v1.w};
            float x2[4] = {v2.x, v2.y, v2.z, v2.w};
            float x3[4] = {v3.x, v3.y, v3.z, v3.w};
            int tb = (h * 4 + i) * 4;
#pragma unroll
            for (int e = 0; e < 4; e++) {
                int t = tb + e;
                ulonglong2 wA = sW [t * 2 + 0];
                ulonglong2 wB = sW [t * 2 + 1];
                ulonglong2 wC = sW2[t * 2 + 0];
                ulonglong2 wD = sW2[t * 2 + 1];
                u64 b0 = pack2(x0[e], x0[e]);
                u64 b1 = pack2(x1[e], x1[e]);
                u64 b2 = pack2(x2[e], x2[e]);
                u64 b3 = pack2(x3[e], x3[e]);
                fma2(acc[0][0], b0, wA.x); fma2(acc[0][1], b0, wA.y);
                fma2(acc[0][2], b0, wB.x); fma2(acc[0][3], b0, wB.y);
                fma2(acc[0][4], b0, wC.x); fma2(acc[0][5], b0, wC.y);
                fma2(acc[0][6], b0, wD.x); fma2(acc[0][7], b0, wD.y);
                fma2(acc[1][0], b1, wA.x); fma2(acc[1][1], b1, wA.y);
                fma2(acc[1][2], b1, wB.x); fma2(acc[1][3], b1, wB.y);
                fma2(acc[1][4], b1, wC.x); fma2(acc[1][5], b1, wC.y);
                fma2(acc[1][6], b1, wD.x); fma2(acc[1][7], b1, wD.y);
                fma2(acc[2][0], b2, wA.x); fma2(acc[2][1], b2, wA.y);
                fma2(acc[2][2], b2, wB.x); fma2(acc[2][3], b2, wB.y);
                fma2(acc[2][4], b2, wC.x); fma2(acc[2][5], b2, wC.y);
                fma2(acc[2][6], b2, wD.x); fma2(acc[2][7], b2, wD.y);
                fma2(acc[3][0], b3, wA.x); fma2(acc[3][1], b3, wA.y);
                fma2(acc[3][2], b3, wB.x); fma2(acc[3][3], b3, wB.y);
                fma2(acc[3][4], b3, wC.x); fma2(acc[3][5], b3, wC.y);
                fma2(acc[3][6], b3, wD.x); fma2(acc[3][7], b3, wD.y);
                ss[0] = fmaf(x0[e], x0[e], ss[0]);
                ss[1] = fmaf(x1[e], x1[e], ss[1]);
                ss[2] = fmaf(x2[e], x2[e], ss[2]);
                ss[3] = fmaf(x3[e], x3[e], ss[3]);
            }
        }
    }

#pragma unroll
    for (int k = 0; k < 4; k++) {
        float scale = rsqrtf(ss[k] * (1.0f / CT) + RMS_EPS);
        float* o = g_Zp + ((size_t)blockIdx.x * ZR3 + r + 128 * k) * CA;
#pragma unroll
        for (int c4 = 0; c4 < 4; c4++) {
            float a0, a1, b0, b1;
            unpack2(acc[k][2 * c4 + 0], a0, a1);
            unpack2(acc[k][2 * c4 + 1], b0, b1);
            reinterpret_cast<float4*>(o)[c4] =
                make_float4(a0 * scale, a1 * scale, b0 * scale, b1 * scale);
        }
    }
}

// ---------------------------------------------------------------------------
// Kernel 1: S_l / S_m projections (R7-exact).
// ---------------------------------------------------------------------------
__global__ void __launch_bounds__(64) sproj_kernel(
    const float* __restrict__ CL,
    const float* __restrict__ Wl,
    const float* __restrict__ Wm)
{
    __shared__ float sX[64 * 68];
    __shared__ ulonglong2 sWl2[512];
    __shared__ ulonglong2 sWm2[512];

    for (int i = threadIdx.x; i < 512; i += 64) {
        int t2 = i >> 3, c2 = i & 7;
        int t0 = 2 * t2, t1 = t0 + 1, c0 = 2 * c2, c1 = c0 + 1;
        sWl2[i] = make_ulonglong2(pack2(Wl[t0 * CA + c0], Wl[t1 * CA + c0]),
                                  pack2(Wl[t0 * CA + c1], Wl[t1 * CA + c1]));
        sWm2[i] = make_ulonglong2(pack2(Wm[t0 * CA + c0], Wm[t1 * CA + c0]),
                                  pack2(Wm[t0 * CA + c1], Wm[t1 * CA + c1]));
    }

    int r = threadIdx.x;
    u64 al2[CA], am2[CA];
#pragma unroll
    for (int c = 0; c < CA; c++) { al2[c] = 0ull; am2[c] = 0ull; }

    const float4* src = reinterpret_cast<const float4*>(CL + (size_t)blockIdx.x * 64 * CT);

#pragma unroll 1
    for (int h = 0; h < 2; h++) {
        __syncthreads();
#pragma unroll 4
        for (int j = threadIdx.x; j < 64 * 16; j += 64) {
            int row = j >> 4, col = j & 15;
            cp_async16(&reinterpret_cast<float4*>(sX)[row * 17 + col],
                       src + row * 32 + h * 16 + col);
        }
        cp_async_wait_all();
        __syncthreads();

        const float4* xr = reinterpret_cast<const float4*>(sX) + r * 17;
#pragma unroll 4
        for (int i = 0; i < 16; i++) {
            float4 v = xr[i];
            u64 p01 = pack2(fmaxf(v.x, 0.f), fmaxf(v.y, 0.f));
            u64 p23 = pack2(fmaxf(v.z, 0.f), fmaxf(v.w, 0.f));
            int t = h * 16 + i;
            const ulonglong2* wla = sWl2 + (2 * t) * 8;
            const ulonglong2* wlb = sWl2 + (2 * t + 1) * 8;
            const ulonglong2* wma = sWm2 + (2 * t) * 8;
            const ulonglong2* wmb = sWm2 + (2 * t + 1) * 8;
#pragma unroll
            for (int c2 = 0; c2 < 8; c2++) {
                ulonglong2 w = wla[c2];
                fma2(al2[2 * c2], p01, w.x);
                fma2(al2[2 * c2 + 1], p01, w.y);
            }
#pragma unroll
            for (int c2 = 0; c2 < 8; c2++) {
                ulonglong2 w = wlb[c2];
                fma2(al2[2 * c2], p23, w.x);
                fma2(al2[2 * c2 + 1], p23, w.y);
            }
#pragma unroll
            for (int c2 = 0; c2 < 8; c2++) {
                ulonglong2 w = wma[c2];
                fma2(am2[2 * c2], p01, w.x);
                fma2(am2[2 * c2 + 1], p01, w.y);
            }
#pragma unroll
            for (int c2 = 0; c2 < 8; c2++) {
                ulonglong2 w = wmb[c2];
                fma2(am2[2 * c2], p23, w.x);
                fma2(am2[2 * c2 + 1], p23, w.y);
            }
        }
    }

    size_t row = (size_t)blockIdx.x * 64 + r;
    float* ol = g_Sl + row * CA;
    float* om = g_Sm + row * CA;
#pragma unroll
    for (int c2 = 0; c2 < 4; c2++) {
        float a0, a1, b0, b1, c0f, c1f, d0, d1;
        unpack2(al2[4 * c2 + 0], a0, a1);
        unpack2(al2[4 * c2 + 1], b0, b1);
        unpack2(al2[4 * c2 + 2], c0f, c1f);
        unpack2(al2[4 * c2 + 3], d0, d1);
        reinterpret_cast<float4*>(ol)[c2] = make_float4(a0 + a1, b0 + b1, c0f + c1f, d0 + d1);
        unpack2(am2[4 * c2 + 0], a0, a1);
        unpack2(am2[4 * c2 + 1], b0, b1);
        unpack2(am2[4 * c2 + 2], c0f, c1f);
        unpack2(am2[4 * c2 + 3], d0, d1);
        reinterpret_cast<float4*>(om)[c2] = make_float4(a0 + a1, b0 + b1, c0f + c1f, d0 + d1);
    }
}

// ---------------------------------------------------------------------------
// Kernel 0: pack geometry + metadata tables (R7-exact).
// ---------------------------------------------------------------------------
__global__ void pack_tables_kernel(
    const float* __restrict__ motif_pos,
    const float* __restrict__ ref_pos,
    const float* __restrict__ is_motif_coord,
    const float* __restrict__ is_motif_seq,
    const int* __restrict__ ref_space_uid,
    const int* __restrict__ tok_idx)
{
    int i = blockIdx.x * blockDim.x + threadIdx.x;
    if (i >= LN) return;
    int uid = ref_space_uid[i] & 1023;
    int seq = (is_motif_seq[i] != 0.f) ? 1 : 0;
    int tok = min(max(tok_idx[i], 0), IN - 1);
    int coord = (is_motif_coord[i] != 0.f) ? 1 : 0;
    int meta = uid | (seq << 10) | (tok << 11) | (coord << 21);
    g_mp[i] = make_float4(motif_pos[i * 3 + 0], motif_pos[i * 3 + 1],
                          motif_pos[i * 3 + 2], __int_as_float(meta));
    g_rp[i] = make_float4(ref_pos[i * 3 + 0], ref_pos[i * 3 + 1],
                          ref_pos[i * 3 + 2], 0.f);
}

// ---------------------------------------------------------------------------
// Kernel 3: pair assembly + residual MLP (R7-exact: direct gathers, best 59us).
// ---------------------------------------------------------------------------
__device__ __forceinline__ void mlp_layer2_x2(const float* in0, const float* in1,
                                              const ulonglong2* W2,
                                              float* out0, float* out1)
{
    u64 a0[CA], a1[CA];
#pragma unroll
    for (int c = 0; c < CA; c++) { a0[c] = 0ull; a1[c] = 0ull; }
#pragma unroll
    for (int j2 = 0; j2 < 8; j2++) {
        u64 r0 = pack2(fmaxf(in0[2 * j2], 0.f), fmaxf(in0[2 * j2 + 1], 0.f));
        u64 r1 = pack2(fmaxf(in1[2 * j2], 0.f), fmaxf(in1[2 * j2 + 1], 0.f));
#pragma unroll
        for (int c2 = 0; c2 < 8; c2++) {
            ulonglong2 w = W2[j2 * 8 + c2];
            fma2(a0[2 * c2], r0, w.x);
            fma2(a0[2 * c2 + 1], r0, w.y);
            fma2(a1[2 * c2], r1, w.x);
            fma2(a1[2 * c2 + 1], r1, w.y);
        }
    }
#pragma unroll
    for (int c = 0; c < CA; c++) {
        float a, b;
        unpack2(a0[c], a, b);
        out0[c] = a + b;
        unpack2(a1[c], a, b);
        out1[c] = a + b;
    }
}

struct PairW {
    const float* sWd_m; const float* sWi_m; const float* sWk_m;
    const float* sWd_r; const float* sWi_r; const float* sWk_r;
};

__device__ __forceinline__ void compute_P(const PairW& cw, int q, int lane,
                                          const int* __restrict__ indices,
                                          float* P)
{
    int b = q / LN;
    int l = q - b * LN;

    int idx = indices[(size_t)q * KN + lane];
    idx = min(max(idx, 0), LN - 1);

    float4 mpk = __ldg(g_mp + idx);
    float4 mpq = __ldg(g_mp + l);
    int mk = __float_as_int(mpk.w);
    int mq = __float_as_int(mpq.w);
    int tk = (mk >> 11) & 1023;
    int tq = (mq >> 11) & 1023;

    const float4* slp = reinterpret_cast<const float4*>(g_Sl + (size_t)q * CA);
    const float4* smp = reinterpret_cast<const float4*>(g_Sm + ((size_t)b * LN + idx) * CA);
    const float4* zp  = reinterpret_cast<const float4*>(g_Zp + ((size_t)tq * IN + tk) * CA);
#pragma unroll
    for (int cc = 0; cc < 4; cc++) {
        float4 a = __ldg(slp + cc);
        float4 m = __ldg(smp + cc);
        float4 z = __ldg(zp + cc);
        P[cc * 4 + 0] = a.x + m.x + z.x;
        P[cc * 4 + 1] = a.y + m.y + z.y;
        P[cc * 4 + 2] = a.z + m.z + z.z;
        P[cc * 4 + 3] = a.w + m.w + z.w;
    }

    int both = mk & mq;
    if ((both >> 21) & 1) {
        float dx = mpq.x - mpk.x;
        float dy = mpq.y - mpk.y;
        float dz = mpq.z - mpk.z;
        float inv = 1.0f / (1.0f + dx * dx + dy * dy + dz * dz);
#pragma unroll
        for (int c = 0; c < CA; c++)
            P[c] += dx * cw.sWd_m[c] + dy * cw.sWd_m[CA + c] + dz * cw.sWd_m[2 * CA + c]
                  + inv * cw.sWi_m[c] + cw.sWk_m[c];
    }

    if (((both >> 10) & 1) && (((mk ^ mq) & 1023) == 0)) {
        float4 rpk = __ldg(g_rp + idx);
        float4 rpq = __ldg(g_rp + l);
        float dx = rpq.x - rpk.x;
        float dy = rpq.y - rpk.y;
        float dz = rpq.z - rpk.z;
        float inv = 1.0f / (1.0f + dx * dx + dy * dy + dz * dz);
#pragma unroll
        for (int c = 0; c < CA; c++)
            P[c] += dx * cw.sWd_r[c] + dy * cw.sWd_r[CA + c] + dz * cw.sWd_r[2 * CA + c]
                  + inv * cw.sWi_r[c] + cw.sWk_r[c];
    }
}

__global__ void __launch_bounds__(128) pair_kernel(
    const int* __restrict__ indices,
    const float* __restrict__ Wd_m, const float* __restrict__ Wi_m, const float* __restrict__ Wk_m,
    const float* __restrict__ Wd_r, const float* __restrict__ Wi_r, const float* __restrict__ Wk_r,
    const float* __restrict__ W1, const float* __restrict__ W2, const float* __restrict__ W3,
    float* __restrict__ out)
{
    __shared__ float sWd_m[3 * CA], sWi_m[CA], sWk_m[CA];
    __shared__ float sWd_r[3 * CA], sWi_r[CA], sWk_r[CA];
    __shared__ ulonglong2 sW1_2[64], sW2_2[64], sW3_2[64];

    int t = threadIdx.x;
    for (int i = t; i < 3 * CA; i += 128) { sWd_m[i] = Wd_m[i]; sWd_r[i] = Wd_r[i]; }
    for (int i = t; i < CA; i += 128) {
        sWi_m[i] = Wi_m[i]; sWk_m[i] = Wk_m[i];
        sWi_r[i] = Wi_r[i]; sWk_r[i] = Wk_r[i];
    }
    for (int i = t; i < 64; i += 128) {
        int j2 = i >> 3, c2 = i & 7;
        int j0 = 2 * j2, j1 = j0 + 1, c0 = 2 * c2, c1 = c0 + 1;
        sW1_2[i] = make_ulonglong2(pack2(W1[j0 * CA + c0], W1[j1 * CA + c0]),
                                   pack2(W1[j0 * CA + c1], W1[j1 * CA + c1]));
        sW2_2[i] = make_ulonglong2(pack2(W2[j0 * CA + c0], W2[j1 * CA + c0]),
                                   pack2(W2[j0 * CA + c1], W2[j1 * CA + c1]));
        sW3_2[i] = make_ulonglong2(pack2(W3[j0 * CA + c0], W3[j1 * CA + c0]),
                                   pack2(W3[j0 * CA + c1], W3[j1 * CA + c1]));
    }
    __syncthreads();

    int warp = blockIdx.x * 4 + (t >> 5);
    int q0 = warp * 2;
    int q1 = q0 + 1;
    if (q1 >= BN * LN) return;
    int lane = t & 31;

    PairW cw{sWd_m, sWi_m, sWk_m, sWd_r, sWi_r, sWk_r};

    float P0[CA], P1[CA];
    compute_P(cw, q0, lane, indices, P0);
    compute_P(cw, q1, lane, indices, P1);

    float h0a[CA], h0b[CA], h1a[CA], h1b[CA];
    mlp_layer2_x2(P0,  P1,  sW1_2, h0a, h1a);
    mlp_layer2_x2(h0a, h1a, sW2_2, h0b, h1b);
    mlp_layer2_x2(h0b, h1b, sW3_2, h0a, h1a);

    float4* op0 = reinterpret_cast<float4*>(out + ((size_t)q0 * KN + lane) * CA);
    float4* op1 = reinterpret_cast<float4*>(out + ((size_t)q1 * KN + lane) * CA);
#pragma unroll
    for (int cc = 0; cc < 4; cc++) {
        op0[cc] = make_float4(P0[cc * 4 + 0] + h0a[cc * 4 + 0],
                              P0[cc * 4 + 1] + h0a[cc * 4 + 1],
                              P0[cc * 4 + 2] + h0a[cc * 4 + 2],
                              P0[cc * 4 + 3] + h0a[cc * 4 + 3]);
        op1[cc] = make_float4(P1[cc * 4 + 0] + h1a[cc * 4 + 0],
                              P1[cc * 4 + 1] + h1a[cc * 4 + 1],
                              P1[cc * 4 + 2] + h1a[cc * 4 + 2],
                              P1[cc * 4 + 3] + h1a[cc * 4 + 3]);
    }
}

// ---------------------------------------------------------------------------
extern "C" void kernel_launch(void* const* d_in, const int* in_sizes, int n_in,
                              void* d_out, int out_size)
{
    const float* motif_pos      = (const float*)d_in[0];
    const float* is_motif_coord = (const float*)d_in[1];
    const float* ref_pos        = (const float*)d_in[2];
    const int*   ref_space_uid  = (const int*)d_in[3];
    const float* is_motif_seq   = (const float*)d_in[4];
    const int*   indices        = (const int*)d_in[5];
    const float* C_L            = (const float*)d_in[6];
    const float* Z              = (const float*)d_in[7];
    const int*   tok_idx        = (const int*)d_in[8];
    const float* W_d_m          = (const float*)d_in[9];
    const float* W_inv_m        = (const float*)d_in[10];
    const float* W_mask_m       = (const float*)d_in[11];
    const float* W_d_r          = (const float*)d_in[12];
    const float* W_inv_r        = (const float*)d_in[13];
    const float* W_mask_r       = (const float*)d_in[14];
    const float* W_single_l     = (const float*)d_in[15];
    const float* W_single_m     = (const float*)d_in[16];
    const float* rms_w          = (const float*)d_in[17];
    const float* W_z            = (const float*)d_in[18];
    const float* W_mlp1         = (const float*)d_in[19];
    const float* W_mlp2         = (const float*)d_in[20];
    const float* W_mlp3         = (const float*)d_in[21];
    float* out = (float*)d_out;

    // --- TMA descriptor for Z (host-side; driver fn via runtime entry point,
    //     no -lcuda link needed). Built every call (cheap, deterministic).
    typedef CUresult (*EncodeFn)(CUtensorMap*, CUtensorMapDataType, cuuint32_t,
                                 void*, const cuuint64_t*, const cuuint64_t*,
                                 const cuuint32_t*, const cuuint32_t*,
                                 CUtensorMapInterleave, CUtensorMapSwizzle,
                                 CUtensorMapL2promotion, CUtensorMapFloatOOBfill);
    static EncodeFn s_encode = nullptr;
    static int s_encode_tried = 0;
    static int s_attr_done = 0;
    if (!s_encode_tried) {
        s_encode_tried = 1;
        cudaDriverEntryPointQueryResult qr;
        void* fn = nullptr;
        if (cudaGetDriverEntryPoint("cuTensorMapEncodeTiled", &fn,
                                    cudaEnableDefault, &qr) == cudaSuccess &&
            qr == cudaDriverEntryPointSuccess) {
            s_encode = (EncodeFn)fn;
        }
    }

    bool use_tma = false;
    CUtensorMap tmap;
    if (s_encode) {
        cuuint64_t dims[2]    = {(cuuint64_t)CT, (cuuint64_t)IN * IN};
        cuuint64_t strides[1] = {(cuuint64_t)CT * sizeof(float)};
        cuuint32_t box[2]     = {32, 256};
        cuuint32_t estr[2]    = {1, 1};
        CUresult res = s_encode(&tmap, CU_TENSOR_MAP_DATA_TYPE_FLOAT32, 2,
                                (void*)Z, dims, strides, box, estr,
                                CU_TENSOR_MAP_INTERLEAVE_NONE,
                                CU_TENSOR_MAP_SWIZZLE_128B,
                                CU_TENSOR_MAP_L2_PROMOTION_L2_128B,
                                CU_TENSOR_MAP_FLOAT_OOB_FILL_NONE);
        use_tma = (res == CUDA_SUCCESS);
    }

    if (use_tma) {
        const int zdyn = 2 * ZCHUNK;   // 131072 B
        if (!s_attr_done) {
            cudaFuncSetAttribute(zproc_kernel,
                                 cudaFuncAttributeMaxDynamicSharedMemorySize, zdyn);
            s_attr_done = 1;
        }
        zproc_kernel<<<(IN * IN) / ZR3, 128, zdyn>>>(tmap, rms_w, W_z);
    } else {
        zproc_fallback_kernel<<<(IN * IN) / ZR3, 128>>>(Z, rms_w, W_z);
    }

    pack_tables_kernel<<<(LN + 127) / 128, 128>>>(motif_pos, ref_pos,
                                                  is_motif_coord, is_motif_seq,
                                                  ref_space_uid, tok_idx);
    sproj_kernel<<<(BN * LN) / 64, 64>>>(C_L, W_single_l, W_single_m);
    pair_kernel<<<(BN * LN) / 8, 128>>>(
        indices,
        W_d_m, W_inv_m, W_mask_m, W_d_r, W_inv_r, W_mask_r,
        W_mlp1, W_mlp2, W_mlp3, out);
}

// round 13
// speedup vs baseline: 1.1198x; 1.1198x over previous
#include <cuda_runtime.h>

#define BN 2
#define LN 12288
#define KN 32
#define IN 768
#define CT 128
#define CA 16
#define RMS_EPS 1e-6f

typedef unsigned long long u64;

// Scratch (allocs are banned; device globals are the sanctioned workaround)
__device__ __align__(128) float g_Sl[BN * LN * CA];   // 1.5 MB
__device__ __align__(128) float g_Sm[BN * LN * CA];   // 1.5 MB
__device__ __align__(128) float g_Zp[(size_t)IN * IN * CA];  // 37.75 MB
__device__ float4 g_mp[LN];                           // motif pos + meta bits
__device__ float4 g_rp[LN];                           // ref pos

// ---- packed f32x2 helpers (sm_100+) ---------------------------------------
__device__ __forceinline__ u64 pack2(float a, float b) {
    u64 v;
    asm("mov.b64 %0, {%1, %2};" : "=l"(v) : "r"(__float_as_uint(a)), "r"(__float_as_uint(b)));
    return v;
}
__device__ __forceinline__ void unpack2(u64 v, float& a, float& b) {
    unsigned x, y;
    asm("mov.b64 {%0, %1}, %2;" : "=r"(x), "=r"(y) : "l"(v));
    a = __uint_as_float(x); b = __uint_as_float(y);
}
__device__ __forceinline__ void fma2(u64& d, u64 a, u64 b) {
    asm("fma.rn.f32x2 %0, %1, %2, %0;" : "+l"(d) : "l"(a), "l"(b));
}
__device__ __forceinline__ void cp_async16(void* smem_dst, const void* gmem_src) {
    unsigned s = (unsigned)__cvta_generic_to_shared(smem_dst);
    asm volatile("cp.async.cg.shared.global [%0], [%1], 16;\n" :: "r"(s), "l"(gmem_src));
}
__device__ __forceinline__ void cp_async_wait_all() {
    asm volatile("cp.async.commit_group;\ncp.async.wait_group 0;\n" ::: "memory");
}

// ---------------------------------------------------------------------------
// Kernel 2: Z_proc = rmsnorm(Z)*rms_w @ W_z.  (R7-exact — best known)
// ---------------------------------------------------------------------------
#define ZR3 512

__global__ void __launch_bounds__(128) zproc_kernel(
    const float* __restrict__ Z,
    const float* __restrict__ rmsw,
    const float* __restrict__ Wz)
{
    __shared__ float4 sX[ZR3 * 5];                     // 40960 B
    __shared__ ulonglong2 sW[CT * 2];                  // cols 0-7
    __shared__ ulonglong2 sW2[CT * 2];                 // cols 8-15

    for (int i = threadIdx.x; i < CT * 2; i += 128) {
        int t = i >> 1, p = i & 1;
        float rw = rmsw[t];
        const float* w = Wz + t * CA;
        sW [i] = make_ulonglong2(pack2(rw * w[4 * p + 0], rw * w[4 * p + 1]),
                                 pack2(rw * w[4 * p + 2], rw * w[4 * p + 3]));
        sW2[i] = make_ulonglong2(pack2(rw * w[8 + 4 * p + 0], rw * w[8 + 4 * p + 1]),
                                 pack2(rw * w[8 + 4 * p + 2], rw * w[8 + 4 * p + 3]));
    }

    int r = threadIdx.x;
    const float4* src = reinterpret_cast<const float4*>(Z) + (size_t)blockIdx.x * ZR3 * 32;

    u64 acc[4][8];
#pragma unroll
    for (int k = 0; k < 4; k++)
#pragma unroll
        for (int c = 0; c < 8; c++) acc[k][c] = 0ull;
    float ss[4] = {0.f, 0.f, 0.f, 0.f};

#pragma unroll 1
    for (int h = 0; h < 8; h++) {
        __syncthreads();
#pragma unroll 4
        for (int j = threadIdx.x; j < ZR3 * 4; j += 128) {
            int row = j >> 2, col = j & 3;
            cp_async16(&sX[row * 5 + col], src + row * 32 + h * 4 + col);
        }
        cp_async_wait_all();
        __syncthreads();

#pragma unroll
        for (int i = 0; i < 4; i++) {
            float4 v0 = sX[(r      ) * 5 + i];
            float4 v1 = sX[(r + 128) * 5 + i];
            float4 v2 = sX[(r + 256) * 5 + i];
            float4 v3 = sX[(r + 384) * 5 + i];
            float x0[4] = {v0.x, v0.y, v0.z, v0.w};
            float x1[4] = {v1.x, v1.y, v1.z, v1.w};
            float x2[4] = {v2.x, v2.y, v2.z, v2.w};
            float x3[4] = {v3.x, v3.y, v3.z, v3.w};
            int tb = (h * 4 + i) * 4;
#pragma unroll
            for (int e = 0; e < 4; e++) {
                int t = tb + e;
                ulonglong2 wA = sW [t * 2 + 0];
                ulonglong2 wB = sW [t * 2 + 1];
                ulonglong2 wC = sW2[t * 2 + 0];
                ulonglong2 wD = sW2[t * 2 + 1];
                u64 b0 = pack2(x0[e], x0[e]);
                u64 b1 = pack2(x1[e], x1[e]);
                u64 b2 = pack2(x2[e], x2[e]);
                u64 b3 = pack2(x3[e], x3[e]);
                fma2(acc[0][0], b0, wA.x); fma2(acc[0][1], b0, wA.y);
                fma2(acc[0][2], b0, wB.x); fma2(acc[0][3], b0, wB.y);
                fma2(acc[0][4], b0, wC.x); fma2(acc[0][5], b0, wC.y);
                fma2(acc[0][6], b0, wD.x); fma2(acc[0][7], b0, wD.y);
                fma2(acc[1][0], b1, wA.x); fma2(acc[1][1], b1, wA.y);
                fma2(acc[1][2], b1, wB.x); fma2(acc[1][3], b1, wB.y);
                fma2(acc[1][4], b1, wC.x); fma2(acc[1][5], b1, wC.y);
                fma2(acc[1][6], b1, wD.x); fma2(acc[1][7], b1, wD.y);
                fma2(acc[2][0], b2, wA.x); fma2(acc[2][1], b2, wA.y);
                fma2(acc[2][2], b2, wB.x); fma2(acc[2][3], b2, wB.y);
                fma2(acc[2][4], b2, wC.x); fma2(acc[2][5], b2, wC.y);
                fma2(acc[2][6], b2, wD.x); fma2(acc[2][7], b2, wD.y);
                fma2(acc[3][0], b3, wA.x); fma2(acc[3][1], b3, wA.y);
                fma2(acc[3][2], b3, wB.x); fma2(acc[3][3], b3, wB.y);
                fma2(acc[3][4], b3, wC.x); fma2(acc[3][5], b3, wC.y);
                fma2(acc[3][6], b3, wD.x); fma2(acc[3][7], b3, wD.y);
                ss[0] = fmaf(x0[e], x0[e], ss[0]);
                ss[1] = fmaf(x1[e], x1[e], ss[1]);
                ss[2] = fmaf(x2[e], x2[e], ss[2]);
                ss[3] = fmaf(x3[e], x3[e], ss[3]);
            }
        }
    }

#pragma unroll
    for (int k = 0; k < 4; k++) {
        float scale = rsqrtf(ss[k] * (1.0f / CT) + RMS_EPS);
        float* o = g_Zp + ((size_t)blockIdx.x * ZR3 + r + 128 * k) * CA;
#pragma unroll
        for (int c4 = 0; c4 < 4; c4++) {
            float a0, a1, b0, b1;
            unpack2(acc[k][2 * c4 + 0], a0, a1);
            unpack2(acc[k][2 * c4 + 1], b0, b1);
            reinterpret_cast<float4*>(o)[c4] =
                make_float4(a0 * scale, a1 * scale, b0 * scale, b1 * scale);
        }
    }
}

// ---------------------------------------------------------------------------
// Kernel 1: S_l / S_m projections (R7-exact).
// ---------------------------------------------------------------------------
__global__ void __launch_bounds__(64) sproj_kernel(
    const float* __restrict__ CL,
    const float* __restrict__ Wl,
    const float* __restrict__ Wm)
{
    __shared__ float sX[64 * 68];
    __shared__ ulonglong2 sWl2[512];
    __shared__ ulonglong2 sWm2[512];

    for (int i = threadIdx.x; i < 512; i += 64) {
        int t2 = i >> 3, c2 = i & 7;
        int t0 = 2 * t2, t1 = t0 + 1, c0 = 2 * c2, c1 = c0 + 1;
        sWl2[i] = make_ulonglong2(pack2(Wl[t0 * CA + c0], Wl[t1 * CA + c0]),
                                  pack2(Wl[t0 * CA + c1], Wl[t1 * CA + c1]));
        sWm2[i] = make_ulonglong2(pack2(Wm[t0 * CA + c0], Wm[t1 * CA + c0]),
                                  pack2(Wm[t0 * CA + c1], Wm[t1 * CA + c1]));
    }

    int r = threadIdx.x;
    u64 al2[CA], am2[CA];
#pragma unroll
    for (int c = 0; c < CA; c++) { al2[c] = 0ull; am2[c] = 0ull; }

    const float4* src = reinterpret_cast<const float4*>(CL + (size_t)blockIdx.x * 64 * CT);

#pragma unroll 1
    for (int h = 0; h < 2; h++) {
        __syncthreads();
#pragma unroll 4
        for (int j = threadIdx.x; j < 64 * 16; j += 64) {
            int row = j >> 4, col = j & 15;
            cp_async16(&reinterpret_cast<float4*>(sX)[row * 17 + col],
                       src + row * 32 + h * 16 + col);
        }
        cp_async_wait_all();
        __syncthreads();

        const float4* xr = reinterpret_cast<const float4*>(sX) + r * 17;
#pragma unroll 4
        for (int i = 0; i < 16; i++) {
            float4 v = xr[i];
            u64 p01 = pack2(fmaxf(v.x, 0.f), fmaxf(v.y, 0.f));
            u64 p23 = pack2(fmaxf(v.z, 0.f), fmaxf(v.w, 0.f));
            int t = h * 16 + i;
            const ulonglong2* wla = sWl2 + (2 * t) * 8;
            const ulonglong2* wlb = sWl2 + (2 * t + 1) * 8;
            const ulonglong2* wma = sWm2 + (2 * t) * 8;
            const ulonglong2* wmb = sWm2 + (2 * t + 1) * 8;
#pragma unroll
            for (int c2 = 0; c2 < 8; c2++) {
                ulonglong2 w = wla[c2];
                fma2(al2[2 * c2], p01, w.x);
                fma2(al2[2 * c2 + 1], p01, w.y);
            }
#pragma unroll
            for (int c2 = 0; c2 < 8; c2++) {
                ulonglong2 w = wlb[c2];
                fma2(al2[2 * c2], p23, w.x);
                fma2(al2[2 * c2 + 1], p23, w.y);
            }
#pragma unroll
            for (int c2 = 0; c2 < 8; c2++) {
                ulonglong2 w = wma[c2];
                fma2(am2[2 * c2], p01, w.x);
                fma2(am2[2 * c2 + 1], p01, w.y);
            }
#pragma unroll
            for (int c2 = 0; c2 < 8; c2++) {
                ulonglong2 w = wmb[c2];
                fma2(am2[2 * c2], p23, w.x);
                fma2(am2[2 * c2 + 1], p23, w.y);
            }
        }
    }

    size_t row = (size_t)blockIdx.x * 64 + r;
    float* ol = g_Sl + row * CA;
    float* om = g_Sm + row * CA;
#pragma unroll
    for (int c2 = 0; c2 < 4; c2++) {
        float a0, a1, b0, b1, c0f, c1f, d0, d1;
        unpack2(al2[4 * c2 + 0], a0, a1);
        unpack2(al2[4 * c2 + 1], b0, b1);
        unpack2(al2[4 * c2 + 2], c0f, c1f);
        unpack2(al2[4 * c2 + 3], d0, d1);
        reinterpret_cast<float4*>(ol)[c2] = make_float4(a0 + a1, b0 + b1, c0f + c1f, d0 + d1);
        unpack2(am2[4 * c2 + 0], a0, a1);
        unpack2(am2[4 * c2 + 1], b0, b1);
        unpack2(am2[4 * c2 + 2], c0f, c1f);
        unpack2(am2[4 * c2 + 3], d0, d1);
        reinterpret_cast<float4*>(om)[c2] = make_float4(a0 + a1, b0 + b1, c0f + c1f, d0 + d1);
    }
}

// ---------------------------------------------------------------------------
// Kernel 0: pack geometry + metadata tables (R7-exact).
// ---------------------------------------------------------------------------
__global__ void pack_tables_kernel(
    const float* __restrict__ motif_pos,
    const float* __restrict__ ref_pos,
    const float* __restrict__ is_motif_coord,
    const float* __restrict__ is_motif_seq,
    const int* __restrict__ ref_space_uid,
    const int* __restrict__ tok_idx)
{
    int i = blockIdx.x * blockDim.x + threadIdx.x;
    if (i >= LN) return;
    int uid = ref_space_uid[i] & 1023;
    int seq = (is_motif_seq[i] != 0.f) ? 1 : 0;
    int tok = min(max(tok_idx[i], 0), IN - 1);
    int coord = (is_motif_coord[i] != 0.f) ? 1 : 0;
    int meta = uid | (seq << 10) | (tok << 11) | (coord << 21);
    g_mp[i] = make_float4(motif_pos[i * 3 + 0], motif_pos[i * 3 + 1],
                          motif_pos[i * 3 + 2], __int_as_float(meta));
    g_rp[i] = make_float4(ref_pos[i * 3 + 0], ref_pos[i * 3 + 1],
                          ref_pos[i * 3 + 2], 0.f);
}

// ---------------------------------------------------------------------------
// Kernel 3: pair assembly + residual MLP (R7-exact: direct gathers).
// ---------------------------------------------------------------------------
__device__ __forceinline__ void mlp_layer2_x2(const float* in0, const float* in1,
                                              const ulonglong2* W2,
                                              float* out0, float* out1)
{
    u64 a0[CA], a1[CA];
#pragma unroll
    for (int c = 0; c < CA; c++) { a0[c] = 0ull; a1[c] = 0ull; }
#pragma unroll
    for (int j2 = 0; j2 < 8; j2++) {
        u64 r0 = pack2(fmaxf(in0[2 * j2], 0.f), fmaxf(in0[2 * j2 + 1], 0.f));
        u64 r1 = pack2(fmaxf(in1[2 * j2], 0.f), fmaxf(in1[2 * j2 + 1], 0.f));
#pragma unroll
        for (int c2 = 0; c2 < 8; c2++) {
            ulonglong2 w = W2[j2 * 8 + c2];
            fma2(a0[2 * c2], r0, w.x);
            fma2(a0[2 * c2 + 1], r0, w.y);
            fma2(a1[2 * c2], r1, w.x);
            fma2(a1[2 * c2 + 1], r1, w.y);
        }
    }
#pragma unroll
    for (int c = 0; c < CA; c++) {
        float a, b;
        unpack2(a0[c], a, b);
        out0[c] = a + b;
        unpack2(a1[c], a, b);
        out1[c] = a + b;
    }
}

struct PairW {
    const float* sWd_m; const float* sWi_m; const float* sWk_m;
    const float* sWd_r; const float* sWi_r; const float* sWk_r;
};

__device__ __forceinline__ void compute_P(const PairW& cw, int q, int lane,
                                          const int* __restrict__ indices,
                                          float* P)
{
    int b = q / LN;
    int l = q - b * LN;

    int idx = indices[(size_t)q * KN + lane];
    idx = min(max(idx, 0), LN - 1);

    float4 mpk = __ldg(g_mp + idx);
    float4 mpq = __ldg(g_mp + l);
    int mk = __float_as_int(mpk.w);
    int mq = __float_as_int(mpq.w);
    int tk = (mk >> 11) & 1023;
    int tq = (mq >> 11) & 1023;

    const float4* slp = reinterpret_cast<const float4*>(g_Sl + (size_t)q * CA);
    const float4* smp = reinterpret_cast<const float4*>(g_Sm + ((size_t)b * LN + idx) * CA);
    const float4* zp  = reinterpret_cast<const float4*>(g_Zp + ((size_t)tq * IN + tk) * CA);
#pragma unroll
    for (int cc = 0; cc < 4; cc++) {
        float4 a = __ldg(slp + cc);
        float4 m = __ldg(smp + cc);
        float4 z = __ldg(zp + cc);
        P[cc * 4 + 0] = a.x + m.x + z.x;
        P[cc * 4 + 1] = a.y + m.y + z.y;
        P[cc * 4 + 2] = a.z + m.z + z.z;
        P[cc * 4 + 3] = a.w + m.w + z.w;
    }

    int both = mk & mq;
    if ((both >> 21) & 1) {
        float dx = mpq.x - mpk.x;
        float dy = mpq.y - mpk.y;
        float dz = mpq.z - mpk.z;
        float inv = 1.0f / (1.0f + dx * dx + dy * dy + dz * dz);
#pragma unroll
        for (int c = 0; c < CA; c++)
            P[c] += dx * cw.sWd_m[c] + dy * cw.sWd_m[CA + c] + dz * cw.sWd_m[2 * CA + c]
                  + inv * cw.sWi_m[c] + cw.sWk_m[c];
    }

    if (((both >> 10) & 1) && (((mk ^ mq) & 1023) == 0)) {
        float4 rpk = __ldg(g_rp + idx);
        float4 rpq = __ldg(g_rp + l);
        float dx = rpq.x - rpk.x;
        float dy = rpq.y - rpk.y;
        float dz = rpq.z - rpk.z;
        float inv = 1.0f / (1.0f + dx * dx + dy * dy + dz * dz);
#pragma unroll
        for (int c = 0; c < CA; c++)
            P[c] += dx * cw.sWd_r[c] + dy * cw.sWd_r[CA + c] + dz * cw.sWd_r[2 * CA + c]
                  + inv * cw.sWi_r[c] + cw.sWk_r[c];
    }
}

__global__ void __launch_bounds__(128) pair_kernel(
    const int* __restrict__ indices,
    const float* __restrict__ Wd_m, const float* __restrict__ Wi_m, const float* __restrict__ Wk_m,
    const float* __restrict__ Wd_r, const float* __restrict__ Wi_r, const float* __restrict__ Wk_r,
    const float* __restrict__ W1, const float* __restrict__ W2, const float* __restrict__ W3,
    float* __restrict__ out)
{
    __shared__ float sWd_m[3 * CA], sWi_m[CA], sWk_m[CA];
    __shared__ float sWd_r[3 * CA], sWi_r[CA], sWk_r[CA];
    __shared__ ulonglong2 sW1_2[64], sW2_2[64], sW3_2[64];

    int t = threadIdx.x;
    for (int i = t; i < 3 * CA; i += 128) { sWd_m[i] = Wd_m[i]; sWd_r[i] = Wd_r[i]; }
    for (int i = t; i < CA; i += 128) {
        sWi_m[i] = Wi_m[i]; sWk_m[i] = Wk_m[i];
        sWi_r[i] = Wi_r[i]; sWk_r[i] = Wk_r[i];
    }
    for (int i = t; i < 64; i += 128) {
        int j2 = i >> 3, c2 = i & 7;
        int j0 = 2 * j2, j1 = j0 + 1, c0 = 2 * c2, c1 = c0 + 1;
        sW1_2[i] = make_ulonglong2(pack2(W1[j0 * CA + c0], W1[j1 * CA + c0]),
                                   pack2(W1[j0 * CA + c1], W1[j1 * CA + c1]));
        sW2_2[i] = make_ulonglong2(pack2(W2[j0 * CA + c0], W2[j1 * CA + c0]),
                                   pack2(W2[j0 * CA + c1], W2[j1 * CA + c1]));
        sW3_2[i] = make_ulonglong2(pack2(W3[j0 * CA + c0], W3[j1 * CA + c0]),
                                   pack2(W3[j0 * CA + c1], W3[j1 * CA + c1]));
    }
    __syncthreads();

    int warp = blockIdx.x * 4 + (t >> 5);
    int q0 = warp * 2;
    int q1 = q0 + 1;
    if (q1 >= BN * LN) return;
    int lane = t & 31;

    PairW cw{sWd_m, sWi_m, sWk_m, sWd_r, sWi_r, sWk_r};

    float P0[CA], P1[CA];
    compute_P(cw, q0, lane, indices, P0);
    compute_P(cw, q1, lane, indices, P1);

    float h0a[CA], h0b[CA], h1a[CA], h1b[CA];
    mlp_layer2_x2(P0,  P1,  sW1_2, h0a, h1a);
    mlp_layer2_x2(h0a, h1a, sW2_2, h0b, h1b);
    mlp_layer2_x2(h0b, h1b, sW3_2, h0a, h1a);

    float4* op0 = reinterpret_cast<float4*>(out + ((size_t)q0 * KN + lane) * CA);
    float4* op1 = reinterpret_cast<float4*>(out + ((size_t)q1 * KN + lane) * CA);
#pragma unroll
    for (int cc = 0; cc < 4; cc++) {
        op0[cc] = make_float4(P0[cc * 4 + 0] + h0a[cc * 4 + 0],
                              P0[cc * 4 + 1] + h0a[cc * 4 + 1],
                              P0[cc * 4 + 2] + h0a[cc * 4 + 2],
                              P0[cc * 4 + 3] + h0a[cc * 4 + 3]);
        op1[cc] = make_float4(P1[cc * 4 + 0] + h1a[cc * 4 + 0],
                              P1[cc * 4 + 1] + h1a[cc * 4 + 1],
                              P1[cc * 4 + 2] + h1a[cc * 4 + 2],
                              P1[cc * 4 + 3] + h1a[cc * 4 + 3]);
    }
}

// ---------------------------------------------------------------------------
// Launch: fork pack+sproj onto a side stream so they run concurrently with
// zproc (they are independent; only pair needs all three). Streams/events are
// created once on the first (uncaptured, correctness) call and reused inside
// graph capture — event fork/join is capture-legal and allocation-free.
// ---------------------------------------------------------------------------
extern "C" void kernel_launch(void* const* d_in, const int* in_sizes, int n_in,
                              void* d_out, int out_size)
{
    const float* motif_pos      = (const float*)d_in[0];
    const float* is_motif_coord = (const float*)d_in[1];
    const float* ref_pos        = (const float*)d_in[2];
    const int*   ref_space_uid  = (const int*)d_in[3];
    const float* is_motif_seq   = (const float*)d_in[4];
    const int*   indices        = (const int*)d_in[5];
    const float* C_L            = (const float*)d_in[6];
    const float* Z              = (const float*)d_in[7];
    const int*   tok_idx        = (const int*)d_in[8];
    const float* W_d_m          = (const float*)d_in[9];
    const float* W_inv_m        = (const float*)d_in[10];
    const float* W_mask_m       = (const float*)d_in[11];
    const float* W_d_r          = (const float*)d_in[12];
    const float* W_inv_r        = (const float*)d_in[13];
    const float* W_mask_r       = (const float*)d_in[14];
    const float* W_single_l     = (const float*)d_in[15];
    const float* W_single_m     = (const float*)d_in[16];
    const float* rms_w          = (const float*)d_in[17];
    const float* W_z            = (const float*)d_in[18];
    const float* W_mlp1         = (const float*)d_in[19];
    const float* W_mlp2         = (const float*)d_in[20];
    const float* W_mlp3         = (const float*)d_in[21];
    float* out = (float*)d_out;

    static cudaStream_t s_side = nullptr;
    static cudaEvent_t s_evFork = nullptr, s_evJoin = nullptr;
    if (!s_side) {
        cudaStreamCreateWithFlags(&s_side, cudaStreamNonBlocking);
        cudaEventCreateWithFlags(&s_evFork, cudaEventDisableTiming);
        cudaEventCreateWithFlags(&s_evJoin, cudaEventDisableTiming);
    }

    // main stream (0): zproc (the long pole)
    // side stream:     pack + sproj, concurrent with zproc
    cudaEventRecord(s_evFork, 0);
    cudaStreamWaitEvent(s_side, s_evFork, 0);

    zproc_kernel<<<(IN * IN) / ZR3, 128>>>(Z, rms_w, W_z);

    pack_tables_kernel<<<(LN + 127) / 128, 128, 0, s_side>>>(
        motif_pos, ref_pos, is_motif_coord, is_motif_seq, ref_space_uid, tok_idx);
    sproj_kernel<<<(BN * LN) / 64, 64, 0, s_side>>>(C_L, W_single_l, W_single_m);
    cudaEventRecord(s_evJoin, s_side);
    cudaStreamWaitEvent(0, s_evJoin, 0);

    pair_kernel<<<(BN * LN) / 8, 128>>>(
        indices,
        W_d_m, W_inv_m, W_mask_m, W_d_r, W_inv_r, W_mask_r,
        W_mlp1, W_mlp2, W_mlp3, out);
}

// round 15
// speedup vs baseline: 1.1255x; 1.0051x over previous
#include <cuda_runtime.h>

#define BN 2
#define LN 12288
#define KN 32
#define IN 768
#define CT 128
#define CA 16
#define RMS_EPS 1e-6f

typedef unsigned long long u64;

// Scratch (allocs are banned; device globals are the sanctioned workaround)
__device__ __align__(128) float g_Sl[BN * LN * CA];   // 1.5 MB
__device__ __align__(128) float g_Sm[BN * LN * CA];   // 1.5 MB
__device__ __align__(128) float g_Zp[(size_t)IN * IN * CA];  // 37.75 MB
__device__ float4 g_mp[LN];                           // motif pos + meta bits
__device__ float4 g_rp[LN];                           // ref pos

// ---- packed f32x2 helpers (sm_100+) ---------------------------------------
__device__ __forceinline__ u64 pack2(float a, float b) {
    u64 v;
    asm("mov.b64 %0, {%1, %2};" : "=l"(v) : "r"(__float_as_uint(a)), "r"(__float_as_uint(b)));
    return v;
}
__device__ __forceinline__ void unpack2(u64 v, float& a, float& b) {
    unsigned x, y;
    asm("mov.b64 {%0, %1}, %2;" : "=r"(x), "=r"(y) : "l"(v));
    a = __uint_as_float(x); b = __uint_as_float(y);
}
__device__ __forceinline__ void fma2(u64& d, u64 a, u64 b) {
    asm("fma.rn.f32x2 %0, %1, %2, %0;" : "+l"(d) : "l"(a), "l"(b));
}
__device__ __forceinline__ void cp_async16(void* smem_dst, const void* gmem_src) {
    unsigned s = (unsigned)__cvta_generic_to_shared(smem_dst);
    asm volatile("cp.async.cg.shared.global [%0], [%1], 16;\n" :: "r"(s), "l"(gmem_src));
}
__device__ __forceinline__ void cp_async_wait_all() {
    asm volatile("cp.async.commit_group;\ncp.async.wait_group 0;\n" ::: "memory");
}

// ---------------------------------------------------------------------------
// Kernel 2: Z_proc = rmsnorm(Z)*rms_w @ W_z.  (R7-exact — best known)
// ---------------------------------------------------------------------------
#define ZR3 512

__global__ void __launch_bounds__(128) zproc_kernel(
    const float* __restrict__ Z,
    const float* __restrict__ rmsw,
    const float* __restrict__ Wz)
{
    __shared__ float4 sX[ZR3 * 5];                     // 40960 B
    __shared__ ulonglong2 sW[CT * 2];                  // cols 0-7
    __shared__ ulonglong2 sW2[CT * 2];                 // cols 8-15

    for (int i = threadIdx.x; i < CT * 2; i += 128) {
        int t = i >> 1, p = i & 1;
        float rw = rmsw[t];
        const float* w = Wz + t * CA;
        sW [i] = make_ulonglong2(pack2(rw * w[4 * p + 0], rw * w[4 * p + 1]),
                                 pack2(rw * w[4 * p + 2], rw * w[4 * p + 3]));
        sW2[i] = make_ulonglong2(pack2(rw * w[8 + 4 * p + 0], rw * w[8 + 4 * p + 1]),
                                 pack2(rw * w[8 + 4 * p + 2], rw * w[8 + 4 * p + 3]));
    }

    int r = threadIdx.x;
    const float4* src = reinterpret_cast<const float4*>(Z) + (size_t)blockIdx.x * ZR3 * 32;

    u64 acc[4][8];
#pragma unroll
    for (int k = 0; k < 4; k++)
#pragma unroll
        for (int c = 0; c < 8; c++) acc[k][c] = 0ull;
    float ss[4] = {0.f, 0.f, 0.f, 0.f};

#pragma unroll 1
    for (int h = 0; h < 8; h++) {
        __syncthreads();
#pragma unroll 4
        for (int j = threadIdx.x; j < ZR3 * 4; j += 128) {
            int row = j >> 2, col = j & 3;
            cp_async16(&sX[row * 5 + col], src + row * 32 + h * 4 + col);
        }
        cp_async_wait_all();
        __syncthreads();

#pragma unroll
        for (int i = 0; i < 4; i++) {
            float4 v0 = sX[(r      ) * 5 + i];
            float4 v1 = sX[(r + 128) * 5 + i];
            float4 v2 = sX[(r + 256) * 5 + i];
            float4 v3 = sX[(r + 384) * 5 + i];
            float x0[4] = {v0.x, v0.y, v0.z, v0.w};
            float x1[4] = {v1.x, v1.y, v1.z, v1.w};
            float x2[4] = {v2.x, v2.y, v2.z, v2.w};
            float x3[4] = {v3.x, v3.y, v3.z, v3.w};
            int tb = (h * 4 + i) * 4;
#pragma unroll
            for (int e = 0; e < 4; e++) {
                int t = tb + e;
                ulonglong2 wA = sW [t * 2 + 0];
                ulonglong2 wB = sW [t * 2 + 1];
                ulonglong2 wC = sW2[t * 2 + 0];
                ulonglong2 wD = sW2[t * 2 + 1];
                u64 b0 = pack2(x0[e], x0[e]);
                u64 b1 = pack2(x1[e], x1[e]);
                u64 b2 = pack2(x2[e], x2[e]);
                u64 b3 = pack2(x3[e], x3[e]);
                fma2(acc[0][0], b0, wA.x); fma2(acc[0][1], b0, wA.y);
                fma2(acc[0][2], b0, wB.x); fma2(acc[0][3], b0, wB.y);
                fma2(acc[0][4], b0, wC.x); fma2(acc[0][5], b0, wC.y);
                fma2(acc[0][6], b0, wD.x); fma2(acc[0][7], b0, wD.y);
                fma2(acc[1][0], b1, wA.x); fma2(acc[1][1], b1, wA.y);
                fma2(acc[1][2], b1, wB.x); fma2(acc[1][3], b1, wB.y);
                fma2(acc[1][4], b1, wC.x); fma2(acc[1][5], b1, wC.y);
                fma2(acc[1][6], b1, wD.x); fma2(acc[1][7], b1, wD.y);
                fma2(acc[2][0], b2, wA.x); fma2(acc[2][1], b2, wA.y);
                fma2(acc[2][2], b2, wB.x); fma2(acc[2][3], b2, wB.y);
                fma2(acc[2][4], b2, wC.x); fma2(acc[2][5], b2, wC.y);
                fma2(acc[2][6], b2, wD.x); fma2(acc[2][7], b2, wD.y);
                fma2(acc[3][0], b3, wA.x); fma2(acc[3][1], b3, wA.y);
                fma2(acc[3][2], b3, wB.x); fma2(acc[3][3], b3, wB.y);
                fma2(acc[3][4], b3, wC.x); fma2(acc[3][5], b3, wC.y);
                fma2(acc[3][6], b3, wD.x); fma2(acc[3][7], b3, wD.y);
                ss[0] = fmaf(x0[e], x0[e], ss[0]);
                ss[1] = fmaf(x1[e], x1[e], ss[1]);
                ss[2] = fmaf(x2[e], x2[e], ss[2]);
                ss[3] = fmaf(x3[e], x3[e], ss[3]);
            }
        }
    }

#pragma unroll
    for (int k = 0; k < 4; k++) {
        float scale = rsqrtf(ss[k] * (1.0f / CT) + RMS_EPS);
        float* o = g_Zp + ((size_t)blockIdx.x * ZR3 + r + 128 * k) * CA;
#pragma unroll
        for (int c4 = 0; c4 < 4; c4++) {
            float a0, a1, b0, b1;
            unpack2(acc[k][2 * c4 + 0], a0, a1);
            unpack2(acc[k][2 * c4 + 1], b0, b1);
            reinterpret_cast<float4*>(o)[c4] =
                make_float4(a0 * scale, a1 * scale, b0 * scale, b1 * scale);
        }
    }
}

// ---------------------------------------------------------------------------
// Kernel 1: S_l / S_m projections (R7-exact).
// ---------------------------------------------------------------------------
__global__ void __launch_bounds__(64) sproj_kernel(
    const float* __restrict__ CL,
    const float* __restrict__ Wl,
    const float* __restrict__ Wm)
{
    __shared__ float sX[64 * 68];
    __shared__ ulonglong2 sWl2[512];
    __shared__ ulonglong2 sWm2[512];

    for (int i = threadIdx.x; i < 512; i += 64) {
        int t2 = i >> 3, c2 = i & 7;
        int t0 = 2 * t2, t1 = t0 + 1, c0 = 2 * c2, c1 = c0 + 1;
        sWl2[i] = make_ulonglong2(pack2(Wl[t0 * CA + c0], Wl[t1 * CA + c0]),
                                  pack2(Wl[t0 * CA + c1], Wl[t1 * CA + c1]));
        sWm2[i] = make_ulonglong2(pack2(Wm[t0 * CA + c0], Wm[t1 * CA + c0]),
                                  pack2(Wm[t0 * CA + c1], Wm[t1 * CA + c1]));
    }

    int r = threadIdx.x;
    u64 al2[CA], am2[CA];
#pragma unroll
    for (int c = 0; c < CA; c++) { al2[c] = 0ull; am2[c] = 0ull; }

    const float4* src = reinterpret_cast<const float4*>(CL + (size_t)blockIdx.x * 64 * CT);

#pragma unroll 1
    for (int h = 0; h < 2; h++) {
        __syncthreads();
#pragma unroll 4
        for (int j = threadIdx.x; j < 64 * 16; j += 64) {
            int row = j >> 4, col = j & 15;
            cp_async16(&reinterpret_cast<float4*>(sX)[row * 17 + col],
                       src + row * 32 + h * 16 + col);
        }
        cp_async_wait_all();
        __syncthreads();

        const float4* xr = reinterpret_cast<const float4*>(sX) + r * 17;
#pragma unroll 4
        for (int i = 0; i < 16; i++) {
            float4 v = xr[i];
            u64 p01 = pack2(fmaxf(v.x, 0.f), fmaxf(v.y, 0.f));
            u64 p23 = pack2(fmaxf(v.z, 0.f), fmaxf(v.w, 0.f));
            int t = h * 16 + i;
            const ulonglong2* wla = sWl2 + (2 * t) * 8;
            const ulonglong2* wlb = sWl2 + (2 * t + 1) * 8;
            const ulonglong2* wma = sWm2 + (2 * t) * 8;
            const ulonglong2* wmb = sWm2 + (2 * t + 1) * 8;
#pragma unroll
            for (int c2 = 0; c2 < 8; c2++) {
                ulonglong2 w = wla[c2];
                fma2(al2[2 * c2], p01, w.x);
                fma2(al2[2 * c2 + 1], p01, w.y);
            }
#pragma unroll
            for (int c2 = 0; c2 < 8; c2++) {
                ulonglong2 w = wlb[c2];
                fma2(al2[2 * c2], p23, w.x);
                fma2(al2[2 * c2 + 1], p23, w.y);
            }
#pragma unroll
            for (int c2 = 0; c2 < 8; c2++) {
                ulonglong2 w = wma[c2];
                fma2(am2[2 * c2], p01, w.x);
                fma2(am2[2 * c2 + 1], p01, w.y);
            }
#pragma unroll
            for (int c2 = 0; c2 < 8; c2++) {
                ulonglong2 w = wmb[c2];
                fma2(am2[2 * c2], p23, w.x);
                fma2(am2[2 * c2 + 1], p23, w.y);
            }
        }
    }

    size_t row = (size_t)blockIdx.x * 64 + r;
    float* ol = g_Sl + row * CA;
    float* om = g_Sm + row * CA;
#pragma unroll
    for (int c2 = 0; c2 < 4; c2++) {
        float a0, a1, b0, b1, c0f, c1f, d0, d1;
        unpack2(al2[4 * c2 + 0], a0, a1);
        unpack2(al2[4 * c2 + 1], b0, b1);
        unpack2(al2[4 * c2 + 2], c0f, c1f);
        unpack2(al2[4 * c2 + 3], d0, d1);
        reinterpret_cast<float4*>(ol)[c2] = make_float4(a0 + a1, b0 + b1, c0f + c1f, d0 + d1);
        unpack2(am2[4 * c2 + 0], a0, a1);
        unpack2(am2[4 * c2 + 1], b0, b1);
        unpack2(am2[4 * c2 + 2], c0f, c1f);
        unpack2(am2[4 * c2 + 3], d0, d1);
        reinterpret_cast<float4*>(om)[c2] = make_float4(a0 + a1, b0 + b1, c0f + c1f, d0 + d1);
    }
}

// ---------------------------------------------------------------------------
// Kernel 0: pack geometry + metadata tables (R7-exact).
// ---------------------------------------------------------------------------
__global__ void pack_tables_kernel(
    const float* __restrict__ motif_pos,
    const float* __restrict__ ref_pos,
    const float* __restrict__ is_motif_coord,
    const float* __restrict__ is_motif_seq,
    const int* __restrict__ ref_space_uid,
    const int* __restrict__ tok_idx)
{
    int i = blockIdx.x * blockDim.x + threadIdx.x;
    if (i >= LN) return;
    int uid = ref_space_uid[i] & 1023;
    int seq = (is_motif_seq[i] != 0.f) ? 1 : 0;
    int tok = min(max(tok_idx[i], 0), IN - 1);
    int coord = (is_motif_coord[i] != 0.f) ? 1 : 0;
    int meta = uid | (seq << 10) | (tok << 11) | (coord << 21);
    g_mp[i] = make_float4(motif_pos[i * 3 + 0], motif_pos[i * 3 + 1],
                          motif_pos[i * 3 + 2], __int_as_float(meta));
    g_rp[i] = make_float4(ref_pos[i * 3 + 0], ref_pos[i * 3 + 1],
                          ref_pos[i * 3 + 2], 0.f);
}

// ---------------------------------------------------------------------------
// Kernel 3: pair assembly + residual MLP. R13 dataflow + COALESCED OUTPUT:
// each query's 2KB out tile is staged in smem (pitch-20 rows, conflict-free
// STS.128) and stored as 4 contiguous warp-STG.128 (4 wf each) instead of
// per-lane strided stores (16 wf each): 64 wf -> ~28 wf per query.
// ---------------------------------------------------------------------------
#define OPITCH 20

__device__ __forceinline__ void mlp_layer2_x2(const float* in0, const float* in1,
                                              const ulonglong2* W2,
                                              float* out0, float* out1)
{
    u64 a0[CA], a1[CA];
#pragma unroll
    for (int c = 0; c < CA; c++) { a0[c] = 0ull; a1[c] = 0ull; }
#pragma unroll
    for (int j2 = 0; j2 < 8; j2++) {
        u64 r0 = pack2(fmaxf(in0[2 * j2], 0.f), fmaxf(in0[2 * j2 + 1], 0.f));
        u64 r1 = pack2(fmaxf(in1[2 * j2], 0.f), fmaxf(in1[2 * j2 + 1], 0.f));
#pragma unroll
        for (int c2 = 0; c2 < 8; c2++) {
            ulonglong2 w = W2[j2 * 8 + c2];
            fma2(a0[2 * c2], r0, w.x);
            fma2(a0[2 * c2 + 1], r0, w.y);
            fma2(a1[2 * c2], r1, w.x);
            fma2(a1[2 * c2 + 1], r1, w.y);
        }
    }
#pragma unroll
    for (int c = 0; c < CA; c++) {
        float a, b;
        unpack2(a0[c], a, b);
        out0[c] = a + b;
        unpack2(a1[c], a, b);
        out1[c] = a + b;
    }
}

struct PairW {
    const float* sWd_m; const float* sWi_m; const float* sWk_m;
    const float* sWd_r; const float* sWi_r; const float* sWk_r;
};

__device__ __forceinline__ void compute_P(const PairW& cw, int q, int lane,
                                          const int* __restrict__ indices,
                                          float* P)
{
    int b = q / LN;
    int l = q - b * LN;

    int idx = indices[(size_t)q * KN + lane];
    idx = min(max(idx, 0), LN - 1);

    float4 mpk = __ldg(g_mp + idx);
    float4 mpq = __ldg(g_mp + l);
    int mk = __float_as_int(mpk.w);
    int mq = __float_as_int(mpq.w);
    int tk = (mk >> 11) & 1023;
    int tq = (mq >> 11) & 1023;

    const float4* slp = reinterpret_cast<const float4*>(g_Sl + (size_t)q * CA);
    const float4* smp = reinterpret_cast<const float4*>(g_Sm + ((size_t)b * LN + idx) * CA);
    const float4* zp  = reinterpret_cast<const float4*>(g_Zp + ((size_t)tq * IN + tk) * CA);
#pragma unroll
    for (int cc = 0; cc < 4; cc++) {
        float4 a = __ldg(slp + cc);
        float4 m = __ldg(smp + cc);
        float4 z = __ldg(zp + cc);
        P[cc * 4 + 0] = a.x + m.x + z.x;
        P[cc * 4 + 1] = a.y + m.y + z.y;
        P[cc * 4 + 2] = a.z + m.z + z.z;
        P[cc * 4 + 3] = a.w + m.w + z.w;
    }

    int both = mk & mq;
    if ((both >> 21) & 1) {
        float dx = mpq.x - mpk.x;
        float dy = mpq.y - mpk.y;
        float dz = mpq.z - mpk.z;
        float inv = 1.0f / (1.0f + dx * dx + dy * dy + dz * dz);
#pragma unroll
        for (int c = 0; c < CA; c++)
            P[c] += dx * cw.sWd_m[c] + dy * cw.sWd_m[CA + c] + dz * cw.sWd_m[2 * CA + c]
                  + inv * cw.sWi_m[c] + cw.sWk_m[c];
    }

    if (((both >> 10) & 1) && (((mk ^ mq) & 1023) == 0)) {
        float4 rpk = __ldg(g_rp + idx);
        float4 rpq = __ldg(g_rp + l);
        float dx = rpq.x - rpk.x;
        float dy = rpq.y - rpk.y;
        float dz = rpq.z - rpk.z;
        float inv = 1.0f / (1.0f + dx * dx + dy * dy + dz * dz);
#pragma unroll
        for (int c = 0; c < CA; c++)
            P[c] += dx * cw.sWd_r[c] + dy * cw.sWd_r[CA + c] + dz * cw.sWd_r[2 * CA + c]
                  + inv * cw.sWi_r[c] + cw.sWk_r[c];
    }
}

// stage one query's 16 out floats/lane into the warp tile, then store the
// 2KB contiguous region as 4 coalesced warp-STG.128.
__device__ __forceinline__ void store_query(float* tile, int lane,
                                            const float* P, const float* h,
                                            float* __restrict__ outq)
{
    __syncwarp();                               // tile free (prev query stored)
    float4* tr = reinterpret_cast<float4*>(tile + lane * OPITCH);
#pragma unroll
    for (int cc = 0; cc < 4; cc++)
        tr[cc] = make_float4(P[cc * 4 + 0] + h[cc * 4 + 0],
                             P[cc * 4 + 1] + h[cc * 4 + 1],
                             P[cc * 4 + 2] + h[cc * 4 + 2],
                             P[cc * 4 + 3] + h[cc * 4 + 3]);
    __syncwarp();                               // tile filled
#pragma unroll
    for (int pass = 0; pass < 4; pass++) {
        int f = pass * 128 + lane * 4;          // float index in [0, 512)
        int k = f >> 4;                         // row in tile
        int c = f & 15;
        float4 v = *reinterpret_cast<const float4*>(tile + k * OPITCH + c);
        reinterpret_cast<float4*>(outq)[pass * 32 + lane] = v;
    }
}

__global__ void __launch_bounds__(128) pair_kernel(
    const int* __restrict__ indices,
    const float* __restrict__ Wd_m, const float* __restrict__ Wi_m, const float* __restrict__ Wk_m,
    const float* __restrict__ Wd_r, const float* __restrict__ Wi_r, const float* __restrict__ Wk_r,
    const float* __restrict__ W1, const float* __restrict__ W2, const float* __restrict__ W3,
    float* __restrict__ out)
{
    __shared__ float sWd_m[3 * CA], sWi_m[CA], sWk_m[CA];
    __shared__ float sWd_r[3 * CA], sWi_r[CA], sWk_r[CA];
    __shared__ ulonglong2 sW1_2[64], sW2_2[64], sW3_2[64];
    __shared__ __align__(16) float sOut[4][32 * OPITCH];    // 10240 B

    int t = threadIdx.x;
    for (int i = t; i < 3 * CA; i += 128) { sWd_m[i] = Wd_m[i]; sWd_r[i] = Wd_r[i]; }
    for (int i = t; i < CA; i += 128) {
        sWi_m[i] = Wi_m[i]; sWk_m[i] = Wk_m[i];
        sWi_r[i] = Wi_r[i]; sWk_r[i] = Wk_r[i];
    }
    for (int i = t; i < 64; i += 128) {
        int j2 = i >> 3, c2 = i & 7;
        int j0 = 2 * j2, j1 = j0 + 1, c0 = 2 * c2, c1 = c0 + 1;
        sW1_2[i] = make_ulonglong2(pack2(W1[j0 * CA + c0], W1[j1 * CA + c0]),
                                   pack2(W1[j0 * CA + c1], W1[j1 * CA + c1]));
        sW2_2[i] = make_ulonglong2(pack2(W2[j0 * CA + c0], W2[j1 * CA + c0]),
                                   pack2(W2[j0 * CA + c1], W2[j1 * CA + c1]));
        sW3_2[i] = make_ulonglong2(pack2(W3[j0 * CA + c0], W3[j1 * CA + c0]),
                                   pack2(W3[j0 * CA + c1], W3[j1 * CA + c1]));
    }
    __syncthreads();

    int wib = t >> 5;
    int warp = blockIdx.x * 4 + wib;
    int q0 = warp * 2;
    int q1 = q0 + 1;
    if (q1 >= BN * LN) return;
    int lane = t & 31;

    PairW cw{sWd_m, sWi_m, sWk_m, sWd_r, sWi_r, sWk_r};

    float P0[CA], P1[CA];
    compute_P(cw, q0, lane, indices, P0);
    compute_P(cw, q1, lane, indices, P1);

    float h0a[CA], h0b[CA], h1a[CA], h1b[CA];
    mlp_layer2_x2(P0,  P1,  sW1_2, h0a, h1a);
    mlp_layer2_x2(h0a, h1a, sW2_2, h0b, h1b);
    mlp_layer2_x2(h0b, h1b, sW3_2, h0a, h1a);

    float* tile = sOut[wib];
    store_query(tile, lane, P0, h0a, out + (size_t)q0 * KN * CA);
    store_query(tile, lane, P1, h1a, out + (size_t)q1 * KN * CA);
}

// ---------------------------------------------------------------------------
// Launch: stream fork (R13) — pack+sproj concurrent with zproc.
// ---------------------------------------------------------------------------
extern "C" void kernel_launch(void* const* d_in, const int* in_sizes, int n_in,
                              void* d_out, int out_size)
{
    const float* motif_pos      = (const float*)d_in[0];
    const float* is_motif_coord = (const float*)d_in[1];
    const float* ref_pos        = (const float*)d_in[2];
    const int*   ref_space_uid  = (const int*)d_in[3];
    const float* is_motif_seq   = (const float*)d_in[4];
    const int*   indices        = (const int*)d_in[5];
    const float* C_L            = (const float*)d_in[6];
    const float* Z              = (const float*)d_in[7];
    const int*   tok_idx        = (const int*)d_in[8];
    const float* W_d_m          = (const float*)d_in[9];
    const float* W_inv_m        = (const float*)d_in[10];
    const float* W_mask_m       = (const float*)d_in[11];
    const float* W_d_r          = (const float*)d_in[12];
    const float* W_inv_r        = (const float*)d_in[13];
    const float* W_mask_r       = (const float*)d_in[14];
    const float* W_single_l     = (const float*)d_in[15];
    const float* W_single_m     = (const float*)d_in[16];
    const float* rms_w          = (const float*)d_in[17];
    const float* W_z            = (const float*)d_in[18];
    const float* W_mlp1         = (const float*)d_in[19];
    const float* W_mlp2         = (const float*)d_in[20];
    const float* W_mlp3         = (const float*)d_in[21];
    float* out = (float*)d_out;

    static cudaStream_t s_side = nullptr;
    static cudaEvent_t s_evFork = nullptr, s_evJoin = nullptr;
    if (!s_side) {
        cudaStreamCreateWithFlags(&s_side, cudaStreamNonBlocking);
        cudaEventCreateWithFlags(&s_evFork, cudaEventDisableTiming);
        cudaEventCreateWithFlags(&s_evJoin, cudaEventDisableTiming);
    }

    cudaEventRecord(s_evFork, 0);
    cudaStreamWaitEvent(s_side, s_evFork, 0);

    zproc_kernel<<<(IN * IN) / ZR3, 128>>>(Z, rms_w, W_z);

    pack_tables_kernel<<<(LN + 127) / 128, 128, 0, s_side>>>(
        motif_pos, ref_pos, is_motif_coord, is_motif_seq, ref_space_uid, tok_idx);
    sproj_kernel<<<(BN * LN) / 64, 64, 0, s_side>>>(C_L, W_single_l, W_single_m);
    cudaEventRecord(s_evJoin, s_side);
    cudaStreamWaitEvent(0, s_evJoin, 0);

    pair_kernel<<<(BN * LN) / 8, 128>>>(
        indices,
        W_d_m, W_inv_m, W_mask_m, W_d_r, W_inv_r, W_mask_r,
        W_mlp1, W_mlp2, W_mlp3, out);
}

// round 17
// speedup vs baseline: 1.1344x; 1.0079x over previous
#include <cuda_runtime.h>

#define BN 2
#define LN 12288
#define KN 32
#define IN 768
#define CT 128
#define CA 16
#define RMS_EPS 1e-6f

typedef unsigned long long u64;

// Scratch (allocs are banned; device globals are the sanctioned workaround)
__device__ __align__(128) float g_Sl[BN * LN * CA];   // 1.5 MB
__device__ __align__(128) float g_Sm[BN * LN * CA];   // 1.5 MB
__device__ __align__(128) float g_Zp[(size_t)IN * IN * CA];  // 37.75 MB
__device__ float4 g_mp[LN];                           // motif pos + meta bits
__device__ float4 g_rp[LN];                           // ref pos

// ---- packed f32x2 helpers (sm_100+) ---------------------------------------
__device__ __forceinline__ u64 pack2(float a, float b) {
    u64 v;
    asm("mov.b64 %0, {%1, %2};" : "=l"(v) : "r"(__float_as_uint(a)), "r"(__float_as_uint(b)));
    return v;
}
__device__ __forceinline__ void unpack2(u64 v, float& a, float& b) {
    unsigned x, y;
    asm("mov.b64 {%0, %1}, %2;" : "=r"(x), "=r"(y) : "l"(v));
    a = __uint_as_float(x); b = __uint_as_float(y);
}
__device__ __forceinline__ void fma2(u64& d, u64 a, u64 b) {
    asm("fma.rn.f32x2 %0, %1, %2, %0;" : "+l"(d) : "l"(a), "l"(b));
}
__device__ __forceinline__ void cp_async16(void* smem_dst, const void* gmem_src) {
    unsigned s = (unsigned)__cvta_generic_to_shared(smem_dst);
    asm volatile("cp.async.cg.shared.global [%0], [%1], 16;\n" :: "r"(s), "l"(gmem_src));
}
__device__ __forceinline__ void cp_async_wait_all() {
    asm volatile("cp.async.commit_group;\ncp.async.wait_group 0;\n" ::: "memory");
}
__device__ __forceinline__ unsigned to_tf32(float v) {
    unsigned r;
    asm("cvt.rna.tf32.f32 %0, %1;" : "=r"(r) : "f"(v));
    return r;
}
__device__ __forceinline__ void mma_tf32(float* c, unsigned a0, unsigned a1,
                                         unsigned a2, unsigned a3,
                                         unsigned b0, unsigned b1) {
    asm volatile(
        "mma.sync.aligned.m16n8k8.row.col.f32.tf32.tf32.f32 "
        "{%0,%1,%2,%3}, {%4,%5,%6,%7}, {%8,%9}, {%0,%1,%2,%3};"
        : "+f"(c[0]), "+f"(c[1]), "+f"(c[2]), "+f"(c[3])
        : "r"(a0), "r"(a1), "r"(a2), "r"(a3), "r"(b0), "r"(b1));
}

// ---------------------------------------------------------------------------
// Kernel 2 (dominant): Z_proc = rmsnorm(Z)*rms_w @ W_z — mma.sync tf32.
// 512 rows/block, 128 threads. Staging identical to R7 (cp.async, 8 chunks of
// 16 cols, pitch 20 words). The scalar GEMM is replaced by m16n8k8 tf32 HMMA:
// warp w owns rows [w*128, w*128+128) = 8 m-tiles x 2 n-tiles; 32 mma per
// chunk per warp. ss stays full-fp32 from the staged tile (thread = row);
// per-row scales staged via smem. Needs >48KB smem -> guarded attribute.
// ---------------------------------------------------------------------------
#define ZR3 512

__global__ void __launch_bounds__(128) zproc_kernel(
    const float* __restrict__ Z,
    const float* __restrict__ rmsw,
    const float* __restrict__ Wz)
{
    extern __shared__ float sX[];                      // 512 * 20 words = 40960 B
    __shared__ float sB[CT * 18];                      // B[k][n] tf32, pitch 18
    __shared__ float sScale[ZR3];

    int tid = threadIdx.x;
    int wid = tid >> 5;
    int lane = tid & 31;
    int gq = lane >> 2;      // group id 0..7
    int tq = lane & 3;       // thread-in-group 0..3

    // build B = (rmsw * Wz), tf32-converted, [k=0..127][n=0..15], pitch 18
    for (int i = tid; i < CT * CA; i += 128) {
        int k = i >> 4, n = i & 15;
        float v = rmsw[k] * Wz[k * CA + n];
        sB[k * 18 + n] = __uint_as_float(to_tf32(v));
    }

    const float4* src = reinterpret_cast<const float4*>(Z) + (size_t)blockIdx.x * ZR3 * 32;

    float acc[8][2][4];
#pragma unroll
    for (int mt = 0; mt < 8; mt++)
#pragma unroll
        for (int nt = 0; nt < 2; nt++)
#pragma unroll
            for (int c = 0; c < 4; c++) acc[mt][nt][c] = 0.f;
    float ss[4] = {0.f, 0.f, 0.f, 0.f};

    int warpRow = wid * 128;

#pragma unroll 1
    for (int h = 0; h < 8; h++) {
        __syncthreads();
#pragma unroll 4
        for (int j = tid; j < ZR3 * 4; j += 128) {
            int row = j >> 2, col = j & 3;
            cp_async16(&reinterpret_cast<float4*>(sX)[row * 5 + col],
                       src + row * 32 + h * 4 + col);
        }
        cp_async_wait_all();
        __syncthreads();

        // ss: thread owns rows tid, tid+128, tid+256, tid+384 (full fp32)
#pragma unroll
        for (int k = 0; k < 4; k++) {
            const float4* xr = reinterpret_cast<const float4*>(sX) + (tid + 128 * k) * 5;
#pragma unroll
            for (int i = 0; i < 4; i++) {
                float4 v = xr[i];
                ss[k] = fmaf(v.x, v.x, ss[k]);
                ss[k] = fmaf(v.y, v.y, ss[k]);
                ss[k] = fmaf(v.z, v.z, ss[k]);
                ss[k] = fmaf(v.w, v.w, ss[k]);
            }
        }

        // mma: 2 k-steps of 8 within this 16-col chunk
#pragma unroll
        for (int kk = 0; kk < 2; kk++) {
            int kglob = h * 16 + kk * 8;
            // B fragments: b[nt][j]: k = kglob + tq + 4j, n = nt*8 + gq
            unsigned b00 = __float_as_uint(sB[(kglob + tq    ) * 18 + gq]);
            unsigned b01 = __float_as_uint(sB[(kglob + tq + 4) * 18 + gq]);
            unsigned b10 = __float_as_uint(sB[(kglob + tq    ) * 18 + 8 + gq]);
            unsigned b11 = __float_as_uint(sB[(kglob + tq + 4) * 18 + 8 + gq]);
            int cb = kk * 8 + tq;
#pragma unroll
            for (int mt = 0; mt < 8; mt++) {
                int r0 = warpRow + mt * 16 + gq;
                unsigned a0 = to_tf32(sX[r0 * 20 + cb]);
                unsigned a1 = to_tf32(sX[(r0 + 8) * 20 + cb]);
                unsigned a2 = to_tf32(sX[r0 * 20 + cb + 4]);
                unsigned a3 = to_tf32(sX[(r0 + 8) * 20 + cb + 4]);
                mma_tf32(acc[mt][0], a0, a1, a2, a3, b00, b01);
                mma_tf32(acc[mt][1], a0, a1, a2, a3, b10, b11);
            }
        }
    }

    // per-row scales
#pragma unroll
    for (int k = 0; k < 4; k++)
        sScale[tid + 128 * k] = rsqrtf(ss[k] * (1.0f / CT) + RMS_EPS);
    __syncthreads();

    // epilogue: C frag (row0 = base+gq, row1 = row0+8; cols 2*tq, 2*tq+1 per n-tile)
    size_t outRow = (size_t)blockIdx.x * ZR3;
#pragma unroll
    for (int mt = 0; mt < 8; mt++) {
        int r0 = warpRow + mt * 16 + gq;
        int r1 = r0 + 8;
        float s0 = sScale[r0];
        float s1 = sScale[r1];
#pragma unroll
        for (int nt = 0; nt < 2; nt++) {
            int col = nt * 8 + 2 * tq;
            float2 v0 = make_float2(acc[mt][nt][0] * s0, acc[mt][nt][1] * s0);
            float2 v1 = make_float2(acc[mt][nt][2] * s1, acc[mt][nt][3] * s1);
            *reinterpret_cast<float2*>(g_Zp + (outRow + r0) * CA + col) = v0;
            *reinterpret_cast<float2*>(g_Zp + (outRow + r1) * CA + col) = v1;
        }
    }
}

// ---------------------------------------------------------------------------
// Kernel 1: S_l / S_m projections (R7-exact).
// ---------------------------------------------------------------------------
__global__ void __launch_bounds__(64) sproj_kernel(
    const float* __restrict__ CL,
    const float* __restrict__ Wl,
    const float* __restrict__ Wm)
{
    __shared__ float sXs[64 * 68];
    __shared__ ulonglong2 sWl2[512];
    __shared__ ulonglong2 sWm2[512];

    for (int i = threadIdx.x; i < 512; i += 64) {
        int t2 = i >> 3, c2 = i & 7;
        int t0 = 2 * t2, t1 = t0 + 1, c0 = 2 * c2, c1 = c0 + 1;
        sWl2[i] = make_ulonglong2(pack2(Wl[t0 * CA + c0], Wl[t1 * CA + c0]),
                                  pack2(Wl[t0 * CA + c1], Wl[t1 * CA + c1]));
        sWm2[i] = make_ulonglong2(pack2(Wm[t0 * CA + c0], Wm[t1 * CA + c0]),
                                  pack2(Wm[t0 * CA + c1], Wm[t1 * CA + c1]));
    }

    int r = threadIdx.x;
    u64 al2[CA], am2[CA];
#pragma unroll
    for (int c = 0; c < CA; c++) { al2[c] = 0ull; am2[c] = 0ull; }

    const float4* src = reinterpret_cast<const float4*>(CL + (size_t)blockIdx.x * 64 * CT);

#pragma unroll 1
    for (int h = 0; h < 2; h++) {
        __syncthreads();
#pragma unroll 4
        for (int j = threadIdx.x; j < 64 * 16; j += 64) {
            int row = j >> 4, col = j & 15;
            cp_async16(&reinterpret_cast<float4*>(sXs)[row * 17 + col],
                       src + row * 32 + h * 16 + col);
        }
        cp_async_wait_all();
        __syncthreads();

        const float4* xr = reinterpret_cast<const float4*>(sXs) + r * 17;
#pragma unroll 4
        for (int i = 0; i < 16; i++) {
            float4 v = xr[i];
            u64 p01 = pack2(fmaxf(v.x, 0.f), fmaxf(v.y, 0.f));
            u64 p23 = pack2(fmaxf(v.z, 0.f), fmaxf(v.w, 0.f));
            int t = h * 16 + i;
            const ulonglong2* wla = sWl2 + (2 * t) * 8;
            const ulonglong2* wlb = sWl2 + (2 * t + 1) * 8;
            const ulonglong2* wma = sWm2 + (2 * t) * 8;
            const ulonglong2* wmb = sWm2 + (2 * t + 1) * 8;
#pragma unroll
            for (int c2 = 0; c2 < 8; c2++) {
                ulonglong2 w = wla[c2];
                fma2(al2[2 * c2], p01, w.x);
                fma2(al2[2 * c2 + 1], p01, w.y);
            }
#pragma unroll
            for (int c2 = 0; c2 < 8; c2++) {
                ulonglong2 w = wlb[c2];
                fma2(al2[2 * c2], p23, w.x);
                fma2(al2[2 * c2 + 1], p23, w.y);
            }
#pragma unroll
            for (int c2 = 0; c2 < 8; c2++) {
                ulonglong2 w = wma[c2];
                fma2(am2[2 * c2], p01, w.x);
                fma2(am2[2 * c2 + 1], p01, w.y);
            }
#pragma unroll
            for (int c2 = 0; c2 < 8; c2++) {
                ulonglong2 w = wmb[c2];
                fma2(am2[2 * c2], p23, w.x);
                fma2(am2[2 * c2 + 1], p23, w.y);
            }
        }
    }

    size_t row = (size_t)blockIdx.x * 64 + r;
    float* ol = g_Sl + row * CA;
    float* om = g_Sm + row * CA;
#pragma unroll
    for (int c2 = 0; c2 < 4; c2++) {
        float a0, a1, b0, b1, c0f, c1f, d0, d1;
        unpack2(al2[4 * c2 + 0], a0, a1);
        unpack2(al2[4 * c2 + 1], b0, b1);
        unpack2(al2[4 * c2 + 2], c0f, c1f);
        unpack2(al2[4 * c2 + 3], d0, d1);
        reinterpret_cast<float4*>(ol)[c2] = make_float4(a0 + a1, b0 + b1, c0f + c1f, d0 + d1);
        unpack2(am2[4 * c2 + 0], a0, a1);
        unpack2(am2[4 * c2 + 1], b0, b1);
        unpack2(am2[4 * c2 + 2], c0f, c1f);
        unpack2(am2[4 * c2 + 3], d0, d1);
        reinterpret_cast<float4*>(om)[c2] = make_float4(a0 + a1, b0 + b1, c0f + c1f, d0 + d1);
    }
}

// ---------------------------------------------------------------------------
// Kernel 0: pack geometry + metadata tables (R7-exact).
// ---------------------------------------------------------------------------
__global__ void pack_tables_kernel(
    const float* __restrict__ motif_pos,
    const float* __restrict__ ref_pos,
    const float* __restrict__ is_motif_coord,
    const float* __restrict__ is_motif_seq,
    const int* __restrict__ ref_space_uid,
    const int* __restrict__ tok_idx)
{
    int i = blockIdx.x * blockDim.x + threadIdx.x;
    if (i >= LN) return;
    int uid = ref_space_uid[i] & 1023;
    int seq = (is_motif_seq[i] != 0.f) ? 1 : 0;
    int tok = min(max(tok_idx[i], 0), IN - 1);
    int coord = (is_motif_coord[i] != 0.f) ? 1 : 0;
    int meta = uid | (seq << 10) | (tok << 11) | (coord << 21);
    g_mp[i] = make_float4(motif_pos[i * 3 + 0], motif_pos[i * 3 + 1],
                          motif_pos[i * 3 + 2], __int_as_float(meta));
    g_rp[i] = make_float4(ref_pos[i * 3 + 0], ref_pos[i * 3 + 1],
                          ref_pos[i * 3 + 2], 0.f);
}

// ---------------------------------------------------------------------------
// Kernel 3: pair assembly + residual MLP (R15-exact: coalesced output).
// ---------------------------------------------------------------------------
#define OPITCH 20

__device__ __forceinline__ void mlp_layer2_x2(const float* in0, const float* in1,
                                              const ulonglong2* W2,
                                              float* out0, float* out1)
{
    u64 a0[CA], a1[CA];
#pragma unroll
    for (int c = 0; c < CA; c++) { a0[c] = 0ull; a1[c] = 0ull; }
#pragma unroll
    for (int j2 = 0; j2 < 8; j2++) {
        u64 r0 = pack2(fmaxf(in0[2 * j2], 0.f), fmaxf(in0[2 * j2 + 1], 0.f));
        u64 r1 = pack2(fmaxf(in1[2 * j2], 0.f), fmaxf(in1[2 * j2 + 1], 0.f));
#pragma unroll
        for (int c2 = 0; c2 < 8; c2++) {
            ulonglong2 w = W2[j2 * 8 + c2];
            fma2(a0[2 * c2], r0, w.x);
            fma2(a0[2 * c2 + 1], r0, w.y);
            fma2(a1[2 * c2], r1, w.x);
            fma2(a1[2 * c2 + 1], r1, w.y);
        }
    }
#pragma unroll
    for (int c = 0; c < CA; c++) {
        float a, b;
        unpack2(a0[c], a, b);
        out0[c] = a + b;
        unpack2(a1[c], a, b);
        out1[c] = a + b;
    }
}

struct PairW {
    const float* sWd_m; const float* sWi_m; const float* sWk_m;
    const float* sWd_r; const float* sWi_r; const float* sWk_r;
};

__device__ __forceinline__ void compute_P(const PairW& cw, int q, int lane,
                                          const int* __restrict__ indices,
                                          float* P)
{
    int b = q / LN;
    int l = q - b * LN;

    int idx = indices[(size_t)q * KN + lane];
    idx = min(max(idx, 0), LN - 1);

    float4 mpk = __ldg(g_mp + idx);
    float4 mpq = __ldg(g_mp + l);
    int mk = __float_as_int(mpk.w);
    int mq = __float_as_int(mpq.w);
    int tk = (mk >> 11) & 1023;
    int tq = (mq >> 11) & 1023;

    const float4* slp = reinterpret_cast<const float4*>(g_Sl + (size_t)q * CA);
    const float4* smp = reinterpret_cast<const float4*>(g_Sm + ((size_t)b * LN + idx) * CA);
    const float4* zp  = reinterpret_cast<const float4*>(g_Zp + ((size_t)tq * IN + tk) * CA);
#pragma unroll
    for (int cc = 0; cc < 4; cc++) {
        float4 a = __ldg(slp + cc);
        float4 m = __ldg(smp + cc);
        float4 z = __ldg(zp + cc);
        P[cc * 4 + 0] = a.x + m.x + z.x;
        P[cc * 4 + 1] = a.y + m.y + z.y;
        P[cc * 4 + 2] = a.z + m.z + z.z;
        P[cc * 4 + 3] = a.w + m.w + z.w;
    }

    int both = mk & mq;
    if ((both >> 21) & 1) {
        float dx = mpq.x - mpk.x;
        float dy = mpq.y - mpk.y;
        float dz = mpq.z - mpk.z;
        float inv = 1.0f / (1.0f + dx * dx + dy * dy + dz * dz);
#pragma unroll
        for (int c = 0; c < CA; c++)
            P[c] += dx * cw.sWd_m[c] + dy * cw.sWd_m[CA + c] + dz * cw.sWd_m[2 * CA + c]
                  + inv * cw.sWi_m[c] + cw.sWk_m[c];
    }

    if (((both >> 10) & 1) && (((mk ^ mq) & 1023) == 0)) {
        float4 rpk = __ldg(g_rp + idx);
        float4 rpq = __ldg(g_rp + l);
        float dx = rpq.x - rpk.x;
        float dy = rpq.y - rpk.y;
        float dz = rpq.z - rpk.z;
        float inv = 1.0f / (1.0f + dx * dx + dy * dy + dz * dz);
#pragma unroll
        for (int c = 0; c < CA; c++)
            P[c] += dx * cw.sWd_r[c] + dy * cw.sWd_r[CA + c] + dz * cw.sWd_r[2 * CA + c]
                  + inv * cw.sWi_r[c] + cw.sWk_r[c];
    }
}

__device__ __forceinline__ void store_query(float* tile, int lane,
                                            const float* P, const float* h,
                                            float* __restrict__ outq)
{
    __syncwarp();
    float4* tr = reinterpret_cast<float4*>(tile + lane * OPITCH);
#pragma unroll
    for (int cc = 0; cc < 4; cc++)
        tr[cc] = make_float4(P[cc * 4 + 0] + h[cc * 4 + 0],
                             P[cc * 4 + 1] + h[cc * 4 + 1],
                             P[cc * 4 + 2] + h[cc * 4 + 2],
                             P[cc * 4 + 3] + h[cc * 4 + 3]);
    __syncwarp();
#pragma unroll
    for (int pass = 0; pass < 4; pass++) {
        int f = pass * 128 + lane * 4;
        int k = f >> 4;
        int c = f & 15;
        float4 v = *reinterpret_cast<const float4*>(tile + k * OPITCH + c);
        reinterpret_cast<float4*>(outq)[pass * 32 + lane] = v;
    }
}

__global__ void __launch_bounds__(128) pair_kernel(
    const int* __restrict__ indices,
    const float* __restrict__ Wd_m, const float* __restrict__ Wi_m, const float* __restrict__ Wk_m,
    const float* __restrict__ Wd_r, const float* __restrict__ Wi_r, const float* __restrict__ Wk_r,
    const float* __restrict__ W1, const float* __restrict__ W2, const float* __restrict__ W3,
    float* __restrict__ out)
{
    __shared__ float sWd_m[3 * CA], sWi_m[CA], sWk_m[CA];
    __shared__ float sWd_r[3 * CA], sWi_r[CA], sWk_r[CA];
    __shared__ ulonglong2 sW1_2[64], sW2_2[64], sW3_2[64];
    __shared__ __align__(16) float sOut[4][32 * OPITCH];

    int t = threadIdx.x;
    for (int i = t; i < 3 * CA; i += 128) { sWd_m[i] = Wd_m[i]; sWd_r[i] = Wd_r[i]; }
    for (int i = t; i < CA; i += 128) {
        sWi_m[i] = Wi_m[i]; sWk_m[i] = Wk_m[i];
        sWi_r[i] = Wi_r[i]; sWk_r[i] = Wk_r[i];
    }
    for (int i = t; i < 64; i += 128) {
        int j2 = i >> 3, c2 = i & 7;
        int j0 = 2 * j2, j1 = j0 + 1, c0 = 2 * c2, c1 = c0 + 1;
        sW1_2[i] = make_ulonglong2(pack2(W1[j0 * CA + c0], W1[j1 * CA + c0]),
                                   pack2(W1[j0 * CA + c1], W1[j1 * CA + c1]));
        sW2_2[i] = make_ulonglong2(pack2(W2[j0 * CA + c0], W2[j1 * CA + c0]),
                                   pack2(W2[j0 * CA + c1], W2[j1 * CA + c1]));
        sW3_2[i] = make_ulonglong2(pack2(W3[j0 * CA + c0], W3[j1 * CA + c0]),
                                   pack2(W3[j0 * CA + c1], W3[j1 * CA + c1]));
    }
    __syncthreads();

    int wib = t >> 5;
    int warp = blockIdx.x * 4 + wib;
    int q0 = warp * 2;
    int q1 = q0 + 1;
    if (q1 >= BN * LN) return;
    int lane = t & 31;

    PairW cw{sWd_m, sWi_m, sWk_m, sWd_r, sWi_r, sWk_r};

    float P0[CA], P1[CA];
    compute_P(cw, q0, lane, indices, P0);
    compute_P(cw, q1, lane, indices, P1);

    float h0a[CA], h0b[CA], h1a[CA], h1b[CA];
    mlp_layer2_x2(P0,  P1,  sW1_2, h0a, h1a);
    mlp_layer2_x2(h0a, h1a, sW2_2, h0b, h1b);
    mlp_layer2_x2(h0b, h1b, sW3_2, h0a, h1a);

    float* tile = sOut[wib];
    store_query(tile, lane, P0, h0a, out + (size_t)q0 * KN * CA);
    store_query(tile, lane, P1, h1a, out + (size_t)q1 * KN * CA);
}

// ---------------------------------------------------------------------------
// Launch: stream fork (R13) — pack+sproj concurrent with zproc.
// ---------------------------------------------------------------------------
extern "C" void kernel_launch(void* const* d_in, const int* in_sizes, int n_in,
                              void* d_out, int out_size)
{
    const float* motif_pos      = (const float*)d_in[0];
    const float* is_motif_coord = (const float*)d_in[1];
    const float* ref_pos        = (const float*)d_in[2];
    const int*   ref_space_uid  = (const int*)d_in[3];
    const float* is_motif_seq   = (const float*)d_in[4];
    const int*   indices        = (const int*)d_in[5];
    const float* C_L            = (const float*)d_in[6];
    const float* Z              = (const float*)d_in[7];
    const int*   tok_idx        = (const int*)d_in[8];
    const float* W_d_m          = (const float*)d_in[9];
    const float* W_inv_m        = (const float*)d_in[10];
    const float* W_mask_m       = (const float*)d_in[11];
    const float* W_d_r          = (const float*)d_in[12];
    const float* W_inv_r        = (const float*)d_in[13];
    const float* W_mask_r       = (const float*)d_in[14];
    const float* W_single_l     = (const float*)d_in[15];
    const float* W_single_m     = (const float*)d_in[16];
    const float* rms_w          = (const float*)d_in[17];
    const float* W_z            = (const float*)d_in[18];
    const float* W_mlp1         = (const float*)d_in[19];
    const float* W_mlp2         = (const float*)d_in[20];
    const float* W_mlp3         = (const float*)d_in[21];
    float* out = (float*)d_out;

    const int zdyn = ZR3 * 20 * (int)sizeof(float);    // 40960 B dynamic
    static int s_attr_done = 0;
    if (!s_attr_done) {
        // static(sB+sScale ~11.3KB) + dynamic(40KB) > 48KB default combined
        // limit -> opt in. Guarded: runs on the uncaptured correctness call.
        cudaFuncSetAttribute(zproc_kernel,
                             cudaFuncAttributeMaxDynamicSharedMemorySize, zdyn);
        s_attr_done = 1;
    }

    static cudaStream_t s_side = nullptr;
    static cudaEvent_t s_evFork = nullptr, s_evJoin = nullptr;
    if (!s_side) {
        cudaStreamCreateWithFlags(&s_side, cudaStreamNonBlocking);
        cudaEventCreateWithFlags(&s_evFork, cudaEventDisableTiming);
        cudaEventCreateWithFlags(&s_evJoin, cudaEventDisableTiming);
    }

    cudaEventRecord(s_evFork, 0);
    cudaStreamWaitEvent(s_side, s_evFork, 0);

    zproc_kernel<<<(IN * IN) / ZR3, 128, zdyn>>>(Z, rms_w, W_z);

    pack_tables_kernel<<<(LN + 127) / 128, 128, 0, s_side>>>(
        motif_pos, ref_pos, is_motif_coord, is_motif_seq, ref_space_uid, tok_idx);
    sproj_kernel<<<(BN * LN) / 64, 64, 0, s_side>>>(C_L, W_single_l, W_single_m);
    cudaEventRecord(s_evJoin, s_side);
    cudaStreamWaitEvent(0, s_evJoin, 0);

    pair_kernel<<<(BN * LN) / 8, 128>>>(
        indices,
        W_d_m, W_inv_m, W_mask_m, W_d_r, W_inv_r, W_mask_r,
        W_mlp1, W_mlp2, W_mlp3, out);
}